// round 1
// baseline (speedup 1.0000x reference)
#include <cuda_runtime.h>
#include <math.h>
#include <stdint.h>

#define NN 10000
#define EE 100000

// ---------------- scratch (device globals; no allocation allowed) ----------
__device__ float g_h[NN * 128];        // ssp(s@W1^T+b1) intermediate
__device__ float g_phi[NN * 384];      // pass-1 node MLP output
__device__ float g_vnew[NN * 384];     // v_new
__device__ float g_snew[NN * 128];     // s_new
__device__ float g_s2[NN * 384];       // pass-2 node MLP output
__device__ float g_w[EE * 384];        // per-edge filter weights (CSR order)
__device__ float g_rbf[EE * 20];       // per-edge radial basis (CSR order)
__device__ float g_unit[EE * 3];       // per-edge unit vector (CSR order)
__device__ int   g_deg[NN];
__device__ int   g_ptr[NN + 1];
__device__ int   g_fill[NN];
__device__ int   g_csr_src[EE];
__device__ int   g_csr_eid[EE];

// ---------------- helpers ---------------------------------------------------
__device__ __forceinline__ float sspf(float x) {
    // softplus(x) - log(2), numerically stable
    float sp = fmaxf(x, 0.0f) + log1pf(expf(-fabsf(x)));
    return sp - 0.69314718055994531f;
}
__device__ __forceinline__ float fcf(float u) {
    // cosine cutoff: 0.5*(cos(pi*u/5)+1) for u<5 else 0
    return (u < 5.0f) ? 0.5f * (cosf(0.6283185307179586f * u) + 1.0f) : 0.0f;
}

// ---------------- CSR build -------------------------------------------------
__global__ void k_zero_deg(int N) {
    int i = blockIdx.x * blockDim.x + threadIdx.x;
    if (i < N) g_deg[i] = 0;
}

__global__ void k_hist(const int* __restrict__ dst, int E) {
    int e = blockIdx.x * blockDim.x + threadIdx.x;
    if (e < E) atomicAdd(&g_deg[dst[e]], 1);
}

__global__ void k_scan(int N) {
    __shared__ int sh[1024];
    __shared__ int carry;
    if (threadIdx.x == 0) carry = 0;
    __syncthreads();
    for (int base = 0; base < N; base += 1024) {
        int i = base + threadIdx.x;
        int v = (i < N) ? g_deg[i] : 0;
        sh[threadIdx.x] = v;
        __syncthreads();
        for (int off = 1; off < 1024; off <<= 1) {
            int t = (threadIdx.x >= off) ? sh[threadIdx.x - off] : 0;
            __syncthreads();
            sh[threadIdx.x] += t;
            __syncthreads();
        }
        int excl = sh[threadIdx.x] - v;
        if (i < N) {
            g_ptr[i] = carry + excl;
            g_fill[i] = carry + excl;
        }
        __syncthreads();
        if (threadIdx.x == 1023) carry += sh[1023];
        __syncthreads();
    }
    if (threadIdx.x == 0) g_ptr[N] = carry;
}

__global__ void k_fill(const int* __restrict__ src, const int* __restrict__ dst, int E) {
    int e = blockIdx.x * blockDim.x + threadIdx.x;
    if (e >= E) return;
    int d = dst[e];
    int pos = atomicAdd(&g_fill[d], 1);
    g_csr_src[pos] = src[e];
    g_csr_eid[pos] = e;
}

// ---------------- per-edge geometry: rbf + unit vector (CSR order) ---------
__global__ void k_edge(const float* __restrict__ x, const int* __restrict__ dst, int E) {
    int p = blockIdx.x * blockDim.x + threadIdx.x;
    if (p >= E) return;
    int e = g_csr_eid[p];
    int sn = g_csr_src[p];
    int dn = dst[e];
    float vx = x[sn * 3 + 0] - x[dn * 3 + 0];
    float vy = x[sn * 3 + 1] - x[dn * 3 + 1];
    float vz = x[sn * 3 + 2] - x[dn * 3 + 2];
    float r = sqrtf(vx * vx + vy * vy + vz * vz + 1e-5f);
    float inv = 1.0f / r;
    g_unit[p * 3 + 0] = vx * inv;
    g_unit[p * 3 + 1] = vy * inv;
    g_unit[p * 3 + 2] = vz * inv;
    float a = 0.6283185307179586f * r;   // pi*r/5
    float c = 0.6324555320336759f * inv; // sqrt(2/5)/r
#pragma unroll
    for (int n = 1; n <= 20; n++)
        g_rbf[p * 20 + (n - 1)] = c * sinf((float)n * a);
}

// ---------------- generic node MLP GEMM: C = act(A[M,128] @ W[NOUT,128]^T + b)
template <int ACT>
__global__ __launch_bounds__(256) void k_mlp(const float* __restrict__ A,
                                             const float* __restrict__ W,
                                             const float* __restrict__ bias,
                                             float* __restrict__ C,
                                             int M, int NOUT) {
    __shared__ float As[16][68];
    __shared__ float Bs[16][68];
    int t = threadIdx.x;
    int m0 = blockIdx.x * 64, n0 = blockIdx.y * 64;
    int tx = t & 15, ty = t >> 4;
    float acc[4][4];
#pragma unroll
    for (int i = 0; i < 4; i++)
#pragma unroll
        for (int j = 0; j < 4; j++) acc[i][j] = 0.0f;

    int lm = t & 63, lk = (t >> 6) << 2;
    for (int k0 = 0; k0 < 128; k0 += 16) {
        __syncthreads();
        {
            int row = m0 + lm;
            float4 av = make_float4(0.f, 0.f, 0.f, 0.f);
            if (row < M) av = *(const float4*)(A + (size_t)row * 128 + k0 + lk);
            As[lk + 0][lm] = av.x; As[lk + 1][lm] = av.y;
            As[lk + 2][lm] = av.z; As[lk + 3][lm] = av.w;
            float4 bv = *(const float4*)(W + (size_t)(n0 + lm) * 128 + k0 + lk);
            Bs[lk + 0][lm] = bv.x; Bs[lk + 1][lm] = bv.y;
            Bs[lk + 2][lm] = bv.z; Bs[lk + 3][lm] = bv.w;
        }
        __syncthreads();
#pragma unroll
        for (int k = 0; k < 16; k++) {
            float4 a = *(const float4*)&As[k][ty << 2];
            float4 b = *(const float4*)&Bs[k][tx << 2];
            acc[0][0] += a.x * b.x; acc[0][1] += a.x * b.y; acc[0][2] += a.x * b.z; acc[0][3] += a.x * b.w;
            acc[1][0] += a.y * b.x; acc[1][1] += a.y * b.y; acc[1][2] += a.y * b.z; acc[1][3] += a.y * b.w;
            acc[2][0] += a.z * b.x; acc[2][1] += a.z * b.y; acc[2][2] += a.z * b.z; acc[2][3] += a.z * b.w;
            acc[3][0] += a.w * b.x; acc[3][1] += a.w * b.y; acc[3][2] += a.w * b.z; acc[3][3] += a.w * b.w;
        }
    }
    float4 bb = *(const float4*)(bias + n0 + (tx << 2));
#pragma unroll
    for (int i = 0; i < 4; i++) {
        int row = m0 + (ty << 2) + i;
        if (row >= M) continue;
        float4 o;
        o.x = acc[i][0] + bb.x; o.y = acc[i][1] + bb.y;
        o.z = acc[i][2] + bb.z; o.w = acc[i][3] + bb.w;
        if (ACT) { o.x = sspf(o.x); o.y = sspf(o.y); o.z = sspf(o.z); o.w = sspf(o.w); }
        *(float4*)(C + (size_t)row * NOUT + n0 + (tx << 2)) = o;
    }
}

// ---------------- w = fc(rbf @ mv_w^T + mv_b): [E,20] x [384,20]^T ---------
__global__ __launch_bounds__(256) void k_w(const float* __restrict__ mvw,
                                           const float* __restrict__ mvb, int E) {
    __shared__ float As[20][68];
    __shared__ float Bs[20][68];
    int t = threadIdx.x;
    int p0 = blockIdx.x * 64, n0 = blockIdx.y * 64;
    int tx = t & 15, ty = t >> 4;
    int lm = t & 63, kq = t >> 6; // kq in 0..3, each covers 5 k's
    {
        int pe = p0 + lm;
#pragma unroll
        for (int j = 0; j < 5; j++) {
            int k = kq * 5 + j;
            As[k][lm] = (pe < E) ? g_rbf[(size_t)pe * 20 + k] : 0.0f;
            Bs[k][lm] = mvw[(size_t)(n0 + lm) * 20 + k];
        }
    }
    __syncthreads();
    float acc[4][4];
#pragma unroll
    for (int i = 0; i < 4; i++)
#pragma unroll
        for (int j = 0; j < 4; j++) acc[i][j] = 0.0f;
#pragma unroll
    for (int k = 0; k < 20; k++) {
        float4 a = *(const float4*)&As[k][ty << 2];
        float4 b = *(const float4*)&Bs[k][tx << 2];
        acc[0][0] += a.x * b.x; acc[0][1] += a.x * b.y; acc[0][2] += a.x * b.z; acc[0][3] += a.x * b.w;
        acc[1][0] += a.y * b.x; acc[1][1] += a.y * b.y; acc[1][2] += a.y * b.z; acc[1][3] += a.y * b.w;
        acc[2][0] += a.z * b.x; acc[2][1] += a.z * b.y; acc[2][2] += a.z * b.z; acc[2][3] += a.z * b.w;
        acc[3][0] += a.w * b.x; acc[3][1] += a.w * b.y; acc[3][2] += a.w * b.z; acc[3][3] += a.w * b.w;
    }
    float4 bb = *(const float4*)(mvb + n0 + (tx << 2));
#pragma unroll
    for (int i = 0; i < 4; i++) {
        int p = p0 + (ty << 2) + i;
        if (p >= E) continue;
        float4 o;
        o.x = fcf(acc[i][0] + bb.x);
        o.y = fcf(acc[i][1] + bb.y);
        o.z = fcf(acc[i][2] + bb.z);
        o.w = fcf(acc[i][3] + bb.w);
        *(float4*)(g_w + (size_t)p * 384 + n0 + (tx << 2)) = o;
    }
}

// ---------------- pass 1 consumer: warp per node ----------------------------
__global__ __launch_bounds__(256) void k_pass1(const float* __restrict__ v,
                                               const float* __restrict__ s, int N) {
    int gw = (blockIdx.x * blockDim.x + threadIdx.x) >> 5;
    int lane = threadIdx.x & 31;
    if (gw >= N) return;
    int beg = g_ptr[gw], end = g_ptr[gw + 1];
    float dv[12];
    float ds4[4];
#pragma unroll
    for (int k = 0; k < 12; k++) dv[k] = 0.0f;
#pragma unroll
    for (int k = 0; k < 4; k++) ds4[k] = 0.0f;

    for (int p = beg; p < end; p++) {
        int sn = g_csr_src[p];
        const float4* phirow = (const float4*)(g_phi + (size_t)sn * 384);
        float4 pv = phirow[lane];
        float4 ps = phirow[32 + lane];
        float4 pr = phirow[64 + lane];
        const float4* wrow = (const float4*)(g_w + (size_t)p * 384);
        float4 wv = wrow[lane];
        float4 ws = wrow[32 + lane];
        float4 wr = wrow[64 + lane];
        const float4* vrow = (const float4*)(v + (size_t)sn * 384);
        float4 a0 = vrow[3 * lane + 0];
        float4 a1 = vrow[3 * lane + 1];
        float4 a2 = vrow[3 * lane + 2];
        float ux = g_unit[3 * p + 0], uy = g_unit[3 * p + 1], uz = g_unit[3 * p + 2];

        float vv0 = pv.x * wv.x, vv1 = pv.y * wv.y, vv2 = pv.z * wv.z, vv3 = pv.w * wv.w;
        float rr0 = pr.x * wr.x, rr1 = pr.y * wr.y, rr2 = pr.z * wr.z, rr3 = pr.w * wr.w;
        ds4[0] += ps.x * ws.x; ds4[1] += ps.y * ws.y;
        ds4[2] += ps.z * ws.z; ds4[3] += ps.w * ws.w;

        dv[0]  += a0.x * vv0 + rr0 * ux;
        dv[1]  += a0.y * vv0 + rr0 * uy;
        dv[2]  += a0.z * vv0 + rr0 * uz;
        dv[3]  += a0.w * vv1 + rr1 * ux;
        dv[4]  += a1.x * vv1 + rr1 * uy;
        dv[5]  += a1.y * vv1 + rr1 * uz;
        dv[6]  += a1.z * vv2 + rr2 * ux;
        dv[7]  += a1.w * vv2 + rr2 * uy;
        dv[8]  += a2.x * vv2 + rr2 * uz;
        dv[9]  += a2.y * vv3 + rr3 * ux;
        dv[10] += a2.z * vv3 + rr3 * uy;
        dv[11] += a2.w * vv3 + rr3 * uz;
    }
    // v_new = v + dv, s_new = s + ds
    const float4* vi = (const float4*)(v + (size_t)gw * 384);
    float4 b0 = vi[3 * lane + 0], b1 = vi[3 * lane + 1], b2 = vi[3 * lane + 2];
    b0.x += dv[0]; b0.y += dv[1]; b0.z += dv[2]; b0.w += dv[3];
    b1.x += dv[4]; b1.y += dv[5]; b1.z += dv[6]; b1.w += dv[7];
    b2.x += dv[8]; b2.y += dv[9]; b2.z += dv[10]; b2.w += dv[11];
    float4* vo = (float4*)(g_vnew + (size_t)gw * 384);
    vo[3 * lane + 0] = b0; vo[3 * lane + 1] = b1; vo[3 * lane + 2] = b2;

    float4 sv = ((const float4*)(s + (size_t)gw * 128))[lane];
    sv.x += ds4[0]; sv.y += ds4[1]; sv.z += ds4[2]; sv.w += ds4[3];
    ((float4*)(g_snew + (size_t)gw * 128))[lane] = sv;
}

// ---------------- pass 2 consumer + final combine: warp per node -----------
__global__ __launch_bounds__(256) void k_pass2(float* __restrict__ out, int N) {
    int gw = (blockIdx.x * blockDim.x + threadIdx.x) >> 5;
    int lane = threadIdx.x & 31;
    if (gw >= N) return;
    int beg = g_ptr[gw], end = g_ptr[gw + 1];
    int deg = end - beg;

    float uv[12];
    float smv[4], sms[4], smss[4];
#pragma unroll
    for (int k = 0; k < 12; k++) uv[k] = 0.0f;
#pragma unroll
    for (int k = 0; k < 4; k++) { smv[k] = 0.0f; sms[k] = 0.0f; smss[k] = 0.0f; }

    for (int p = beg; p < end; p++) {
        int sn = g_csr_src[p];
        const float4* vrow = (const float4*)(g_vnew + (size_t)sn * 384);
        float4 a0 = vrow[3 * lane + 0];
        float4 a1 = vrow[3 * lane + 1];
        float4 a2 = vrow[3 * lane + 2];
        uv[0] += a0.x; uv[1] += a0.y; uv[2]  += a0.z; uv[3]  += a0.w;
        uv[4] += a1.x; uv[5] += a1.y; uv[6]  += a1.z; uv[7]  += a1.w;
        uv[8] += a2.x; uv[9] += a2.y; uv[10] += a2.z; uv[11] += a2.w;
        const float4* srow = (const float4*)(g_s2 + (size_t)sn * 384);
        float4 q0 = srow[lane];
        float4 q1 = srow[32 + lane];
        float4 q2 = srow[64 + lane];
        smv[0]  += q0.x; smv[1]  += q0.y; smv[2]  += q0.z; smv[3]  += q0.w;
        sms[0]  += q1.x; sms[1]  += q1.y; sms[2]  += q1.z; sms[3]  += q1.w;
        smss[0] += q2.x; smss[1] += q2.y; smss[2] += q2.z; smss[3] += q2.w;
    }
    float inv = 1.0f / fmaxf((float)deg, 1.0f);
#pragma unroll
    for (int k = 0; k < 12; k++) uv[k] *= inv;
    float avv[4], asv[4], ass[4];
#pragma unroll
    for (int j = 0; j < 4; j++) {
        avv[j] = smv[j] * inv;
        asv[j] = sms[j] * inv;
        ass[j] = smss[j] * inv;
    }

    // vector output: v_new + uv * avv
    const float4* vi = (const float4*)(g_vnew + (size_t)gw * 384);
    float4 b0 = vi[3 * lane + 0], b1 = vi[3 * lane + 1], b2 = vi[3 * lane + 2];
    b0.x += uv[0] * avv[0]; b0.y += uv[1]  * avv[0]; b0.z += uv[2]  * avv[0];
    b0.w += uv[3] * avv[1]; b1.x += uv[4]  * avv[1]; b1.y += uv[5]  * avv[1];
    b1.z += uv[6] * avv[2]; b1.w += uv[7]  * avv[2]; b2.x += uv[8]  * avv[2];
    b2.y += uv[9] * avv[3]; b2.z += uv[10] * avv[3]; b2.w += uv[11] * avv[3];
    float4* vo = (float4*)(out + (size_t)gw * 384);
    vo[3 * lane + 0] = b0; vo[3 * lane + 1] = b1; vo[3 * lane + 2] = b2;

    // scalar output: s_new + (|uv|^2/(|uv|^2+eps))*asv + ass
    float4 sn4 = ((const float4*)(g_snew + (size_t)gw * 128))[lane];
    float so[4];
#pragma unroll
    for (int j = 0; j < 4; j++) {
        float sx = uv[3 * j + 0], sy = uv[3 * j + 1], sz = uv[3 * j + 2];
        float ssq = sx * sx + sy * sy + sz * sz;
        float ratio = ssq / (ssq + 1e-5f);
        so[j] = ratio * asv[j] + ass[j];
    }
    sn4.x += so[0]; sn4.y += so[1]; sn4.z += so[2]; sn4.w += so[3];
    ((float4*)(out + (size_t)N * 384 + (size_t)gw * 128))[lane] = sn4;
}

// ---------------- launcher --------------------------------------------------
extern "C" void kernel_launch(void* const* d_in, const int* in_sizes, int n_in,
                              void* d_out, int out_size) {
    const float* x     = (const float*)d_in[0];
    const float* v     = (const float*)d_in[1];
    const float* s     = (const float*)d_in[2];
    const float* ms1_w = (const float*)d_in[3];
    const float* ms1_b = (const float*)d_in[4];
    const float* ms2_w = (const float*)d_in[5];
    const float* ms2_b = (const float*)d_in[6];
    const float* mv_w  = (const float*)d_in[7];
    const float* mv_b  = (const float*)d_in[8];
    const float* us1_w = (const float*)d_in[9];
    const float* us1_b = (const float*)d_in[10];
    const float* us2_w = (const float*)d_in[11];
    const float* us2_b = (const float*)d_in[12];
    const int*   src   = (const int*)d_in[13];
    const int*   dst   = (const int*)d_in[14];
    float* out = (float*)d_out;

    int N = in_sizes[0] / 3;
    int E = in_sizes[13];

    float *p_h, *p_phi, *p_vnew, *p_snew, *p_s2;
    cudaGetSymbolAddress((void**)&p_h, g_h);
    cudaGetSymbolAddress((void**)&p_phi, g_phi);
    cudaGetSymbolAddress((void**)&p_vnew, g_vnew);
    cudaGetSymbolAddress((void**)&p_snew, g_snew);
    cudaGetSymbolAddress((void**)&p_s2, g_s2);

    // CSR build
    k_zero_deg<<<(N + 255) / 256, 256>>>(N);
    k_hist<<<(E + 255) / 256, 256>>>(dst, E);
    k_scan<<<1, 1024>>>(N);
    k_fill<<<(E + 255) / 256, 256>>>(src, dst, E);

    // per-edge geometry (CSR order)
    k_edge<<<(E + 255) / 256, 256>>>(x, dst, E);

    // pass-1 node MLP: phi = ssp(s@ms1^T+b1)@ms2^T+b2
    {
        dim3 ga((N + 63) / 64, 128 / 64);
        k_mlp<1><<<ga, 256>>>(s, ms1_w, ms1_b, p_h, N, 128);
        dim3 gb((N + 63) / 64, 384 / 64);
        k_mlp<0><<<gb, 256>>>(p_h, ms2_w, ms2_b, p_phi, N, 384);
    }

    // per-edge filter weights
    {
        dim3 gw_((E + 63) / 64, 384 / 64);
        k_w<<<gw_, 256>>>(mv_w, mv_b, E);
    }

    // pass-1 reduce (warp per node)
    k_pass1<<<(N * 32 + 255) / 256, 256>>>(v, s, N);

    // pass-2 node MLP on s_new
    {
        dim3 ga((N + 63) / 64, 128 / 64);
        k_mlp<1><<<ga, 256>>>(p_snew, us1_w, us1_b, p_h, N, 128);
        dim3 gb((N + 63) / 64, 384 / 64);
        k_mlp<0><<<gb, 256>>>(p_h, us2_w, us2_b, p_s2, N, 384);
    }

    // pass-2 reduce + final combine
    k_pass2<<<(N * 32 + 255) / 256, 256>>>(out, N);
}

// round 2
// speedup vs baseline: 1.3758x; 1.3758x over previous
#include <cuda_runtime.h>
#include <cuda_fp16.h>
#include <math.h>
#include <stdint.h>

#define NN 10000
#define EE 100000

// ---------------- scratch (device globals; no allocation allowed) ----------
__device__ float g_h[NN * 128];        // ssp(s@W1^T+b1) intermediate
__device__ float g_phi[NN * 384];      // pass-1 node MLP output
__device__ float g_vnew[NN * 384];     // v_new
__device__ float g_snew[NN * 128];     // s_new
__device__ float g_s2[NN * 384];       // pass-2 node MLP output
__device__ __half g_wh[EE * 384];      // per-edge filter weights, fp16 (CSR order)
__device__ float g_rbf[EE * 20];       // per-edge radial basis (CSR order)
__device__ float g_unit[EE * 3];       // per-edge unit vector (CSR order)
__device__ int   g_deg[NN];
__device__ int   g_ptr[NN + 1];
__device__ int   g_fill[NN];
__device__ int   g_csr_src[EE];
__device__ int   g_csr_eid[EE];

// ---------------- helpers ---------------------------------------------------
__device__ __forceinline__ float sspf(float x) {
    float sp = fmaxf(x, 0.0f) + log1pf(expf(-fabsf(x)));
    return sp - 0.69314718055994531f;
}
__device__ __forceinline__ float fcf(float u) {
    // cosine cutoff: 0.5*(cos(pi*u/5)+1) for u<5 else 0 (|arg| modest -> __cosf fine)
    return (u < 5.0f) ? 0.5f * (__cosf(0.6283185307179586f * u) + 1.0f) : 0.0f;
}
__device__ __forceinline__ uint32_t f2tf32(float f) {
    uint32_t r;
    asm("cvt.rna.tf32.f32 %0, %1;" : "=r"(r) : "f"(f));
    return r;
}
__device__ __forceinline__ void mma_tf32(float c[4], const uint32_t a[4], const uint32_t b[2]) {
    asm volatile(
        "mma.sync.aligned.m16n8k8.row.col.f32.tf32.tf32.f32 "
        "{%0,%1,%2,%3},{%4,%5,%6,%7},{%8,%9},{%0,%1,%2,%3};"
        : "+f"(c[0]), "+f"(c[1]), "+f"(c[2]), "+f"(c[3])
        : "r"(a[0]), "r"(a[1]), "r"(a[2]), "r"(a[3]), "r"(b[0]), "r"(b[1]));
}

// ---------------- CSR build -------------------------------------------------
__global__ void k_zero_deg(int N) {
    int i = blockIdx.x * blockDim.x + threadIdx.x;
    if (i < N) g_deg[i] = 0;
}

__global__ void k_hist(const int* __restrict__ dst, int E) {
    int e = blockIdx.x * blockDim.x + threadIdx.x;
    if (e < E) atomicAdd(&g_deg[dst[e]], 1);
}

__global__ void k_scan(int N) {
    __shared__ int sh[1024];
    __shared__ int carry;
    if (threadIdx.x == 0) carry = 0;
    __syncthreads();
    for (int base = 0; base < N; base += 1024) {
        int i = base + threadIdx.x;
        int v = (i < N) ? g_deg[i] : 0;
        sh[threadIdx.x] = v;
        __syncthreads();
        for (int off = 1; off < 1024; off <<= 1) {
            int t = (threadIdx.x >= off) ? sh[threadIdx.x - off] : 0;
            __syncthreads();
            sh[threadIdx.x] += t;
            __syncthreads();
        }
        int excl = sh[threadIdx.x] - v;
        if (i < N) {
            g_ptr[i] = carry + excl;
            g_fill[i] = carry + excl;
        }
        __syncthreads();
        if (threadIdx.x == 1023) carry += sh[1023];
        __syncthreads();
    }
    if (threadIdx.x == 0) g_ptr[N] = carry;
}

__global__ void k_fill(const int* __restrict__ src, const int* __restrict__ dst, int E) {
    int e = blockIdx.x * blockDim.x + threadIdx.x;
    if (e >= E) return;
    int d = dst[e];
    int pos = atomicAdd(&g_fill[d], 1);
    g_csr_src[pos] = src[e];
    g_csr_eid[pos] = e;
}

// ---------------- per-edge geometry: rbf + unit vector (CSR order) ---------
__global__ void k_edge(const float* __restrict__ x, const int* __restrict__ dst, int E) {
    int p = blockIdx.x * blockDim.x + threadIdx.x;
    if (p >= E) return;
    int e = g_csr_eid[p];
    int sn = g_csr_src[p];
    int dn = dst[e];
    float vx = x[sn * 3 + 0] - x[dn * 3 + 0];
    float vy = x[sn * 3 + 1] - x[dn * 3 + 1];
    float vz = x[sn * 3 + 2] - x[dn * 3 + 2];
    float r = sqrtf(vx * vx + vy * vy + vz * vz + 1e-5f);
    float inv = 1.0f / r;
    g_unit[p * 3 + 0] = vx * inv;
    g_unit[p * 3 + 1] = vy * inv;
    g_unit[p * 3 + 2] = vz * inv;
    float a = 0.6283185307179586f * r;   // pi*r/5
    float c = 0.6324555320336759f * inv; // sqrt(2/5)/r
#pragma unroll
    for (int n = 1; n <= 20; n++)
        g_rbf[p * 20 + (n - 1)] = c * sinf((float)n * a);
}

// ---------------- tf32 tensor-core node MLP: C = act(A[M,128] @ W[NOUT,128]^T + b)
// block = 128 threads (4 warps, 2x2), tile 64x64, K staged in halves of 64.
template <int ACT>
__global__ __launch_bounds__(128) void k_mlp_tc(const float* __restrict__ A,
                                                const float* __restrict__ W,
                                                const float* __restrict__ bias,
                                                float* __restrict__ C,
                                                int M, int NOUT) {
    __shared__ uint32_t As[64 * 68];
    __shared__ uint32_t Ws[64 * 68];
    int t = threadIdx.x;
    int warp = t >> 5, lane = t & 31;
    int gid = lane >> 2, tig = lane & 3;
    int wm = warp & 1, wn = warp >> 1;
    int m0 = blockIdx.x * 64, n0 = blockIdx.y * 64;

    float acc[2][4][4];
#pragma unroll
    for (int i = 0; i < 2; i++)
#pragma unroll
        for (int j = 0; j < 4; j++)
#pragma unroll
            for (int k = 0; k < 4; k++) acc[i][j][k] = 0.0f;

    for (int ks = 0; ks < 128; ks += 64) {
        __syncthreads();
        // stage A and W tiles (64 rows x 64 cols) as tf32 bits
        for (int i = t; i < 64 * 16; i += 128) {
            int row = i >> 4, c4 = (i & 15) << 2;
            float4 av = make_float4(0.f, 0.f, 0.f, 0.f);
            if (m0 + row < M)
                av = *(const float4*)(A + (size_t)(m0 + row) * 128 + ks + c4);
            uint32_t* da = &As[row * 68 + c4];
            da[0] = f2tf32(av.x); da[1] = f2tf32(av.y);
            da[2] = f2tf32(av.z); da[3] = f2tf32(av.w);
            float4 wv = *(const float4*)(W + (size_t)(n0 + row) * 128 + ks + c4);
            uint32_t* dw = &Ws[row * 68 + c4];
            dw[0] = f2tf32(wv.x); dw[1] = f2tf32(wv.y);
            dw[2] = f2tf32(wv.z); dw[3] = f2tf32(wv.w);
        }
        __syncthreads();
#pragma unroll
        for (int kc = 0; kc < 64; kc += 8) {
            uint32_t a[2][4], b[4][2];
#pragma unroll
            for (int ma = 0; ma < 2; ma++) {
                int r = wm * 32 + ma * 16 + gid;
                a[ma][0] = As[r * 68 + kc + tig];
                a[ma][1] = As[(r + 8) * 68 + kc + tig];
                a[ma][2] = As[r * 68 + kc + tig + 4];
                a[ma][3] = As[(r + 8) * 68 + kc + tig + 4];
            }
#pragma unroll
            for (int na = 0; na < 4; na++) {
                int cl = wn * 32 + na * 8 + gid;
                b[na][0] = Ws[cl * 68 + kc + tig];
                b[na][1] = Ws[cl * 68 + kc + tig + 4];
            }
#pragma unroll
            for (int ma = 0; ma < 2; ma++)
#pragma unroll
                for (int na = 0; na < 4; na++)
                    mma_tf32(acc[ma][na], a[ma], b[na]);
        }
    }
    // epilogue
#pragma unroll
    for (int ma = 0; ma < 2; ma++) {
#pragma unroll
        for (int na = 0; na < 4; na++) {
            int m = m0 + wm * 32 + ma * 16 + gid;
            int n = n0 + wn * 32 + na * 8 + 2 * tig;
            float bx = bias[n], by = bias[n + 1];
            float o0 = acc[ma][na][0] + bx, o1 = acc[ma][na][1] + by;
            float o2 = acc[ma][na][2] + bx, o3 = acc[ma][na][3] + by;
            if (ACT) { o0 = sspf(o0); o1 = sspf(o1); o2 = sspf(o2); o3 = sspf(o3); }
            if (m < M) *(float2*)(C + (size_t)m * NOUT + n) = make_float2(o0, o1);
            if (m + 8 < M) *(float2*)(C + (size_t)(m + 8) * NOUT + n) = make_float2(o2, o3);
        }
    }
}

// ---------------- tf32 edge filter GEMM: w = fc(rbf[E,20] @ mv_w[384,20]^T + b)
// K=20 padded to 24 (3 k-chunks of 8). Output stored fp16.
__global__ __launch_bounds__(128) void k_w_tc(const float* __restrict__ mvw,
                                              const float* __restrict__ mvb, int E) {
    __shared__ uint32_t As[64 * 28];
    __shared__ uint32_t Bs[64 * 28];
    int t = threadIdx.x;
    int warp = t >> 5, lane = t & 31;
    int gid = lane >> 2, tig = lane & 3;
    int wm = warp & 1, wn = warp >> 1;
    int p0 = blockIdx.x * 64, n0 = blockIdx.y * 64;

    // fill K columns 0..19
    for (int i = t; i < 64 * 20; i += 128) {
        int row = i / 20, c = i - row * 20;
        float av = (p0 + row < E) ? g_rbf[(size_t)(p0 + row) * 20 + c] : 0.0f;
        As[row * 28 + c] = f2tf32(av);
        Bs[row * 28 + c] = f2tf32(mvw[(size_t)(n0 + row) * 20 + c]);
    }
    // zero pad columns 20..27
    for (int i = t; i < 64 * 8; i += 128) {
        int row = i >> 3, c = 20 + (i & 7);
        As[row * 28 + c] = 0;
        Bs[row * 28 + c] = 0;
    }
    __syncthreads();

    float acc[2][4][4];
#pragma unroll
    for (int i = 0; i < 2; i++)
#pragma unroll
        for (int j = 0; j < 4; j++)
#pragma unroll
            for (int k = 0; k < 4; k++) acc[i][j][k] = 0.0f;

#pragma unroll
    for (int kc = 0; kc < 24; kc += 8) {
        uint32_t a[2][4], b[4][2];
#pragma unroll
        for (int ma = 0; ma < 2; ma++) {
            int r = wm * 32 + ma * 16 + gid;
            a[ma][0] = As[r * 28 + kc + tig];
            a[ma][1] = As[(r + 8) * 28 + kc + tig];
            a[ma][2] = As[r * 28 + kc + tig + 4];
            a[ma][3] = As[(r + 8) * 28 + kc + tig + 4];
        }
#pragma unroll
        for (int na = 0; na < 4; na++) {
            int cl = wn * 32 + na * 8 + gid;
            b[na][0] = Bs[cl * 28 + kc + tig];
            b[na][1] = Bs[cl * 28 + kc + tig + 4];
        }
#pragma unroll
        for (int ma = 0; ma < 2; ma++)
#pragma unroll
            for (int na = 0; na < 4; na++)
                mma_tf32(acc[ma][na], a[ma], b[na]);
    }

#pragma unroll
    for (int ma = 0; ma < 2; ma++) {
#pragma unroll
        for (int na = 0; na < 4; na++) {
            int p = p0 + wm * 32 + ma * 16 + gid;
            int n = n0 + wn * 32 + na * 8 + 2 * tig;
            float bx = mvb[n], by = mvb[n + 1];
            float o0 = fcf(acc[ma][na][0] + bx), o1 = fcf(acc[ma][na][1] + by);
            float o2 = fcf(acc[ma][na][2] + bx), o3 = fcf(acc[ma][na][3] + by);
            if (p < E)
                *(__half2*)(g_wh + (size_t)p * 384 + n) = __floats2half2_rn(o0, o1);
            if (p + 8 < E)
                *(__half2*)(g_wh + (size_t)(p + 8) * 384 + n) = __floats2half2_rn(o2, o3);
        }
    }
}

// ---------------- pass 1 consumer: warp per node ----------------------------
__global__ __launch_bounds__(256) void k_pass1(const float* __restrict__ v,
                                               const float* __restrict__ s, int N) {
    int gw = (blockIdx.x * blockDim.x + threadIdx.x) >> 5;
    int lane = threadIdx.x & 31;
    if (gw >= N) return;
    int beg = g_ptr[gw], end = g_ptr[gw + 1];
    float dv[12];
    float ds4[4];
#pragma unroll
    for (int k = 0; k < 12; k++) dv[k] = 0.0f;
#pragma unroll
    for (int k = 0; k < 4; k++) ds4[k] = 0.0f;

    for (int p = beg; p < end; p++) {
        int sn = g_csr_src[p];
        const float4* phirow = (const float4*)(g_phi + (size_t)sn * 384);
        float4 pv = phirow[lane];
        float4 ps = phirow[32 + lane];
        float4 pr = phirow[64 + lane];
        const __half* wr = g_wh + (size_t)p * 384;
        int2 q0 = *(const int2*)(wr + 4 * lane);
        int2 q1 = *(const int2*)(wr + 128 + 4 * lane);
        int2 q2 = *(const int2*)(wr + 256 + 4 * lane);
        float2 wv01 = __half22float2(*(__half2*)&q0.x);
        float2 wv23 = __half22float2(*(__half2*)&q0.y);
        float2 ws01 = __half22float2(*(__half2*)&q1.x);
        float2 ws23 = __half22float2(*(__half2*)&q1.y);
        float2 wr01 = __half22float2(*(__half2*)&q2.x);
        float2 wr23 = __half22float2(*(__half2*)&q2.y);
        const float4* vrow = (const float4*)(v + (size_t)sn * 384);
        float4 a0 = vrow[3 * lane + 0];
        float4 a1 = vrow[3 * lane + 1];
        float4 a2 = vrow[3 * lane + 2];
        float ux = g_unit[3 * p + 0], uy = g_unit[3 * p + 1], uz = g_unit[3 * p + 2];

        float vv0 = pv.x * wv01.x, vv1 = pv.y * wv01.y, vv2 = pv.z * wv23.x, vv3 = pv.w * wv23.y;
        float rr0 = pr.x * wr01.x, rr1 = pr.y * wr01.y, rr2 = pr.z * wr23.x, rr3 = pr.w * wr23.y;
        ds4[0] += ps.x * ws01.x; ds4[1] += ps.y * ws01.y;
        ds4[2] += ps.z * ws23.x; ds4[3] += ps.w * ws23.y;

        dv[0]  += a0.x * vv0 + rr0 * ux;
        dv[1]  += a0.y * vv0 + rr0 * uy;
        dv[2]  += a0.z * vv0 + rr0 * uz;
        dv[3]  += a0.w * vv1 + rr1 * ux;
        dv[4]  += a1.x * vv1 + rr1 * uy;
        dv[5]  += a1.y * vv1 + rr1 * uz;
        dv[6]  += a1.z * vv2 + rr2 * ux;
        dv[7]  += a1.w * vv2 + rr2 * uy;
        dv[8]  += a2.x * vv2 + rr2 * uz;
        dv[9]  += a2.y * vv3 + rr3 * ux;
        dv[10] += a2.z * vv3 + rr3 * uy;
        dv[11] += a2.w * vv3 + rr3 * uz;
    }
    const float4* vi = (const float4*)(v + (size_t)gw * 384);
    float4 b0 = vi[3 * lane + 0], b1 = vi[3 * lane + 1], b2 = vi[3 * lane + 2];
    b0.x += dv[0]; b0.y += dv[1]; b0.z += dv[2]; b0.w += dv[3];
    b1.x += dv[4]; b1.y += dv[5]; b1.z += dv[6]; b1.w += dv[7];
    b2.x += dv[8]; b2.y += dv[9]; b2.z += dv[10]; b2.w += dv[11];
    float4* vo = (float4*)(g_vnew + (size_t)gw * 384);
    vo[3 * lane + 0] = b0; vo[3 * lane + 1] = b1; vo[3 * lane + 2] = b2;

    float4 sv = ((const float4*)(s + (size_t)gw * 128))[lane];
    sv.x += ds4[0]; sv.y += ds4[1]; sv.z += ds4[2]; sv.w += ds4[3];
    ((float4*)(g_snew + (size_t)gw * 128))[lane] = sv;
}

// ---------------- pass 2 consumer + final combine: warp per node -----------
__global__ __launch_bounds__(256) void k_pass2(float* __restrict__ out, int N) {
    int gw = (blockIdx.x * blockDim.x + threadIdx.x) >> 5;
    int lane = threadIdx.x & 31;
    if (gw >= N) return;
    int beg = g_ptr[gw], end = g_ptr[gw + 1];
    int deg = end - beg;

    float uv[12];
    float smv[4], sms[4], smss[4];
#pragma unroll
    for (int k = 0; k < 12; k++) uv[k] = 0.0f;
#pragma unroll
    for (int k = 0; k < 4; k++) { smv[k] = 0.0f; sms[k] = 0.0f; smss[k] = 0.0f; }

    for (int p = beg; p < end; p++) {
        int sn = g_csr_src[p];
        const float4* vrow = (const float4*)(g_vnew + (size_t)sn * 384);
        float4 a0 = vrow[3 * lane + 0];
        float4 a1 = vrow[3 * lane + 1];
        float4 a2 = vrow[3 * lane + 2];
        uv[0] += a0.x; uv[1] += a0.y; uv[2]  += a0.z; uv[3]  += a0.w;
        uv[4] += a1.x; uv[5] += a1.y; uv[6]  += a1.z; uv[7]  += a1.w;
        uv[8] += a2.x; uv[9] += a2.y; uv[10] += a2.z; uv[11] += a2.w;
        const float4* srow = (const float4*)(g_s2 + (size_t)sn * 384);
        float4 q0 = srow[lane];
        float4 q1 = srow[32 + lane];
        float4 q2 = srow[64 + lane];
        smv[0]  += q0.x; smv[1]  += q0.y; smv[2]  += q0.z; smv[3]  += q0.w;
        sms[0]  += q1.x; sms[1]  += q1.y; sms[2]  += q1.z; sms[3]  += q1.w;
        smss[0] += q2.x; smss[1] += q2.y; smss[2] += q2.z; smss[3] += q2.w;
    }
    float inv = 1.0f / fmaxf((float)deg, 1.0f);
#pragma unroll
    for (int k = 0; k < 12; k++) uv[k] *= inv;
    float avv[4], asv[4], ass[4];
#pragma unroll
    for (int j = 0; j < 4; j++) {
        avv[j] = smv[j] * inv;
        asv[j] = sms[j] * inv;
        ass[j] = smss[j] * inv;
    }

    const float4* vi = (const float4*)(g_vnew + (size_t)gw * 384);
    float4 b0 = vi[3 * lane + 0], b1 = vi[3 * lane + 1], b2 = vi[3 * lane + 2];
    b0.x += uv[0] * avv[0]; b0.y += uv[1]  * avv[0]; b0.z += uv[2]  * avv[0];
    b0.w += uv[3] * avv[1]; b1.x += uv[4]  * avv[1]; b1.y += uv[5]  * avv[1];
    b1.z += uv[6] * avv[2]; b1.w += uv[7]  * avv[2]; b2.x += uv[8]  * avv[2];
    b2.y += uv[9] * avv[3]; b2.z += uv[10] * avv[3]; b2.w += uv[11] * avv[3];
    float4* vo = (float4*)(out + (size_t)gw * 384);
    vo[3 * lane + 0] = b0; vo[3 * lane + 1] = b1; vo[3 * lane + 2] = b2;

    float4 sn4 = ((const float4*)(g_snew + (size_t)gw * 128))[lane];
    float so[4];
#pragma unroll
    for (int j = 0; j < 4; j++) {
        float sx = uv[3 * j + 0], sy = uv[3 * j + 1], sz = uv[3 * j + 2];
        float ssq = sx * sx + sy * sy + sz * sz;
        float ratio = ssq / (ssq + 1e-5f);
        so[j] = ratio * asv[j] + ass[j];
    }
    sn4.x += so[0]; sn4.y += so[1]; sn4.z += so[2]; sn4.w += so[3];
    ((float4*)(out + (size_t)N * 384 + (size_t)gw * 128))[lane] = sn4;
}

// ---------------- launcher --------------------------------------------------
extern "C" void kernel_launch(void* const* d_in, const int* in_sizes, int n_in,
                              void* d_out, int out_size) {
    const float* x     = (const float*)d_in[0];
    const float* v     = (const float*)d_in[1];
    const float* s     = (const float*)d_in[2];
    const float* ms1_w = (const float*)d_in[3];
    const float* ms1_b = (const float*)d_in[4];
    const float* ms2_w = (const float*)d_in[5];
    const float* ms2_b = (const float*)d_in[6];
    const float* mv_w  = (const float*)d_in[7];
    const float* mv_b  = (const float*)d_in[8];
    const float* us1_w = (const float*)d_in[9];
    const float* us1_b = (const float*)d_in[10];
    const float* us2_w = (const float*)d_in[11];
    const float* us2_b = (const float*)d_in[12];
    const int*   src   = (const int*)d_in[13];
    const int*   dst   = (const int*)d_in[14];
    float* out = (float*)d_out;

    int N = in_sizes[0] / 3;
    int E = in_sizes[13];

    float *p_h, *p_phi, *p_vnew, *p_snew, *p_s2;
    cudaGetSymbolAddress((void**)&p_h, g_h);
    cudaGetSymbolAddress((void**)&p_phi, g_phi);
    cudaGetSymbolAddress((void**)&p_vnew, g_vnew);
    cudaGetSymbolAddress((void**)&p_snew, g_snew);
    cudaGetSymbolAddress((void**)&p_s2, g_s2);

    // CSR build
    k_zero_deg<<<(N + 255) / 256, 256>>>(N);
    k_hist<<<(E + 255) / 256, 256>>>(dst, E);
    k_scan<<<1, 1024>>>(N);
    k_fill<<<(E + 255) / 256, 256>>>(src, dst, E);

    // per-edge geometry (CSR order)
    k_edge<<<(E + 255) / 256, 256>>>(x, dst, E);

    // pass-1 node MLP (tf32 tensor cores)
    {
        dim3 ga((N + 63) / 64, 128 / 64);
        k_mlp_tc<1><<<ga, 128>>>(s, ms1_w, ms1_b, p_h, N, 128);
        dim3 gb((N + 63) / 64, 384 / 64);
        k_mlp_tc<0><<<gb, 128>>>(p_h, ms2_w, ms2_b, p_phi, N, 384);
    }

    // per-edge filter weights (tf32 tensor cores, fp16 output)
    {
        dim3 gw_((E + 63) / 64, 384 / 64);
        k_w_tc<<<gw_, 128>>>(mv_w, mv_b, E);
    }

    // pass-1 reduce (warp per node)
    k_pass1<<<(N * 32 + 255) / 256, 256>>>(v, s, N);

    // pass-2 node MLP on s_new (tf32 tensor cores)
    {
        dim3 ga((N + 63) / 64, 128 / 64);
        k_mlp_tc<1><<<ga, 128>>>(p_snew, us1_w, us1_b, p_h, N, 128);
        dim3 gb((N + 63) / 64, 384 / 64);
        k_mlp_tc<0><<<gb, 128>>>(p_h, us2_w, us2_b, p_s2, N, 384);
    }

    // pass-2 reduce + final combine
    k_pass2<<<(N * 32 + 255) / 256, 256>>>(out, N);
}

// round 3
// speedup vs baseline: 1.4311x; 1.0401x over previous
#include <cuda_runtime.h>
#include <cuda_fp16.h>
#include <math.h>
#include <stdint.h>

#define NN 10000
#define EE 100000

// ---------------- scratch (device globals; no allocation allowed) ----------
__device__ float  g_h[NN * 128];       // ssp(s@W1^T+b1) intermediate (fp32)
__device__ __half g_phih[NN * 384];    // pass-1 node MLP output (fp16)
__device__ float  g_vnew[NN * 384];    // v_new fp32 (own-node reads + precision)
__device__ __half g_vnewh[NN * 384];   // v_new fp16 shadow (pass-2 gathers)
__device__ float  g_snew[NN * 128];    // s_new
__device__ __half g_s2h[NN * 384];     // pass-2 node MLP output (fp16)
__device__ __half g_wh[EE * 384];      // per-edge filter weights, fp16 (CSR order)
__device__ float  g_rbf[EE * 20];      // per-edge radial basis (CSR order)
__device__ float  g_unit[EE * 3];      // per-edge unit vector (CSR order)
__device__ int    g_deg[NN];
__device__ int    g_ptr[NN + 1];
__device__ int    g_fill[NN];
__device__ int    g_csr_src[EE];
__device__ int    g_csr_eid[EE];

// ---------------- helpers ---------------------------------------------------
__device__ __forceinline__ float sspf(float x) {
    float sp = fmaxf(x, 0.0f) + log1pf(expf(-fabsf(x)));
    return sp - 0.69314718055994531f;
}
__device__ __forceinline__ float fcf(float u) {
    return (u < 5.0f) ? 0.5f * (__cosf(0.6283185307179586f * u) + 1.0f) : 0.0f;
}
__device__ __forceinline__ uint32_t f2tf32(float f) {
    uint32_t r;
    asm("cvt.rna.tf32.f32 %0, %1;" : "=r"(r) : "f"(f));
    return r;
}
__device__ __forceinline__ void mma_tf32(float c[4], const uint32_t a[4], const uint32_t b[2]) {
    asm volatile(
        "mma.sync.aligned.m16n8k8.row.col.f32.tf32.tf32.f32 "
        "{%0,%1,%2,%3},{%4,%5,%6,%7},{%8,%9},{%0,%1,%2,%3};"
        : "+f"(c[0]), "+f"(c[1]), "+f"(c[2]), "+f"(c[3])
        : "r"(a[0]), "r"(a[1]), "r"(a[2]), "r"(a[3]), "r"(b[0]), "r"(b[1]));
}

// ---------------- CSR build -------------------------------------------------
__global__ void k_hist(const int* __restrict__ dst, int E) {
    int e = blockIdx.x * blockDim.x + threadIdx.x;
    if (e < E) atomicAdd(&g_deg[dst[e]], 1);
}

__global__ void k_scan(int N) {
    __shared__ int sh[1024];
    __shared__ int carry;
    if (threadIdx.x == 0) carry = 0;
    __syncthreads();
    for (int base = 0; base < N; base += 1024) {
        int i = base + threadIdx.x;
        int v = (i < N) ? g_deg[i] : 0;
        sh[threadIdx.x] = v;
        __syncthreads();
        for (int off = 1; off < 1024; off <<= 1) {
            int t = (threadIdx.x >= off) ? sh[threadIdx.x - off] : 0;
            __syncthreads();
            sh[threadIdx.x] += t;
            __syncthreads();
        }
        int excl = sh[threadIdx.x] - v;
        if (i < N) {
            g_ptr[i] = carry + excl;
            g_fill[i] = carry + excl;
        }
        __syncthreads();
        if (threadIdx.x == 1023) carry += sh[1023];
        __syncthreads();
    }
    if (threadIdx.x == 0) g_ptr[N] = carry;
}

__global__ void k_fill(const int* __restrict__ src, const int* __restrict__ dst, int E) {
    int e = blockIdx.x * blockDim.x + threadIdx.x;
    if (e >= E) return;
    int d = dst[e];
    int pos = atomicAdd(&g_fill[d], 1);
    g_csr_src[pos] = src[e];
    g_csr_eid[pos] = e;
}

// ---------------- per-edge geometry: rbf (Chebyshev recurrence) + unit vec --
__global__ void k_edge(const float* __restrict__ x, const int* __restrict__ dst, int E) {
    int p = blockIdx.x * blockDim.x + threadIdx.x;
    if (p >= E) return;
    int e = g_csr_eid[p];
    int sn = g_csr_src[p];
    int dn = dst[e];
    float vx = x[sn * 3 + 0] - x[dn * 3 + 0];
    float vy = x[sn * 3 + 1] - x[dn * 3 + 1];
    float vz = x[sn * 3 + 2] - x[dn * 3 + 2];
    float r = sqrtf(vx * vx + vy * vy + vz * vz + 1e-5f);
    float inv = 1.0f / r;
    g_unit[p * 3 + 0] = vx * inv;
    g_unit[p * 3 + 1] = vy * inv;
    g_unit[p * 3 + 2] = vz * inv;
    float a = 0.6283185307179586f * r;   // pi*r/5
    float c = 0.6324555320336759f * inv; // sqrt(2/5)/r
    float sa, ca;
    sincosf(a, &sa, &ca);
    float twoc = 2.0f * ca;
    float s_nm1 = 0.0f, s_n = sa;       // sin(0), sin(a)
#pragma unroll
    for (int n = 1; n <= 20; n++) {
        g_rbf[p * 20 + (n - 1)] = c * s_n;
        float s_np1 = twoc * s_n - s_nm1;
        s_nm1 = s_n;
        s_n = s_np1;
    }
}

// ---------------- tf32 tensor-core node MLP: C = act(A[M,128] @ W[NOUT,128]^T + b)
// block = 128 threads (4 warps, 2x2), tile 64x64. HALF_OUT: write fp16.
template <int ACT, int HALF_OUT>
__global__ __launch_bounds__(128) void k_mlp_tc(const float* __restrict__ A,
                                                const float* __restrict__ W,
                                                const float* __restrict__ bias,
                                                void* __restrict__ Cv,
                                                int M, int NOUT) {
    __shared__ uint32_t As[64 * 68];
    __shared__ uint32_t Ws[64 * 68];
    int t = threadIdx.x;
    int warp = t >> 5, lane = t & 31;
    int gid = lane >> 2, tig = lane & 3;
    int wm = warp & 1, wn = warp >> 1;
    int m0 = blockIdx.x * 64, n0 = blockIdx.y * 64;

    float acc[2][4][4];
#pragma unroll
    for (int i = 0; i < 2; i++)
#pragma unroll
        for (int j = 0; j < 4; j++)
#pragma unroll
            for (int k = 0; k < 4; k++) acc[i][j][k] = 0.0f;

    for (int ks = 0; ks < 128; ks += 64) {
        __syncthreads();
        for (int i = t; i < 64 * 16; i += 128) {
            int row = i >> 4, c4 = (i & 15) << 2;
            float4 av = make_float4(0.f, 0.f, 0.f, 0.f);
            if (m0 + row < M)
                av = *(const float4*)(A + (size_t)(m0 + row) * 128 + ks + c4);
            uint32_t* da = &As[row * 68 + c4];
            da[0] = f2tf32(av.x); da[1] = f2tf32(av.y);
            da[2] = f2tf32(av.z); da[3] = f2tf32(av.w);
            float4 wv = *(const float4*)(W + (size_t)(n0 + row) * 128 + ks + c4);
            uint32_t* dw = &Ws[row * 68 + c4];
            dw[0] = f2tf32(wv.x); dw[1] = f2tf32(wv.y);
            dw[2] = f2tf32(wv.z); dw[3] = f2tf32(wv.w);
        }
        __syncthreads();
#pragma unroll
        for (int kc = 0; kc < 64; kc += 8) {
            uint32_t a[2][4], b[4][2];
#pragma unroll
            for (int ma = 0; ma < 2; ma++) {
                int r = wm * 32 + ma * 16 + gid;
                a[ma][0] = As[r * 68 + kc + tig];
                a[ma][1] = As[(r + 8) * 68 + kc + tig];
                a[ma][2] = As[r * 68 + kc + tig + 4];
                a[ma][3] = As[(r + 8) * 68 + kc + tig + 4];
            }
#pragma unroll
            for (int na = 0; na < 4; na++) {
                int cl = wn * 32 + na * 8 + gid;
                b[na][0] = Ws[cl * 68 + kc + tig];
                b[na][1] = Ws[cl * 68 + kc + tig + 4];
            }
#pragma unroll
            for (int ma = 0; ma < 2; ma++)
#pragma unroll
                for (int na = 0; na < 4; na++)
                    mma_tf32(acc[ma][na], a[ma], b[na]);
        }
    }
#pragma unroll
    for (int ma = 0; ma < 2; ma++) {
#pragma unroll
        for (int na = 0; na < 4; na++) {
            int m = m0 + wm * 32 + ma * 16 + gid;
            int n = n0 + wn * 32 + na * 8 + 2 * tig;
            float bx = bias[n], by = bias[n + 1];
            float o0 = acc[ma][na][0] + bx, o1 = acc[ma][na][1] + by;
            float o2 = acc[ma][na][2] + bx, o3 = acc[ma][na][3] + by;
            if (ACT) { o0 = sspf(o0); o1 = sspf(o1); o2 = sspf(o2); o3 = sspf(o3); }
            if (HALF_OUT) {
                __half* C = (__half*)Cv;
                if (m < M) *(__half2*)(C + (size_t)m * NOUT + n) = __floats2half2_rn(o0, o1);
                if (m + 8 < M) *(__half2*)(C + (size_t)(m + 8) * NOUT + n) = __floats2half2_rn(o2, o3);
            } else {
                float* C = (float*)Cv;
                if (m < M) *(float2*)(C + (size_t)m * NOUT + n) = make_float2(o0, o1);
                if (m + 8 < M) *(float2*)(C + (size_t)(m + 8) * NOUT + n) = make_float2(o2, o3);
            }
        }
    }
}

// ---------------- tf32 edge filter GEMM: w = fc(rbf[E,20] @ mv_w[384,20]^T + b)
__global__ __launch_bounds__(128) void k_w_tc(const float* __restrict__ mvw,
                                              const float* __restrict__ mvb, int E) {
    __shared__ uint32_t As[64 * 28];
    __shared__ uint32_t Bs[64 * 28];
    int t = threadIdx.x;
    int warp = t >> 5, lane = t & 31;
    int gid = lane >> 2, tig = lane & 3;
    int wm = warp & 1, wn = warp >> 1;
    int p0 = blockIdx.x * 64, n0 = blockIdx.y * 64;

    for (int i = t; i < 64 * 20; i += 128) {
        int row = i / 20, c = i - row * 20;
        float av = (p0 + row < E) ? g_rbf[(size_t)(p0 + row) * 20 + c] : 0.0f;
        As[row * 28 + c] = f2tf32(av);
        Bs[row * 28 + c] = f2tf32(mvw[(size_t)(n0 + row) * 20 + c]);
    }
    for (int i = t; i < 64 * 8; i += 128) {
        int row = i >> 3, c = 20 + (i & 7);
        As[row * 28 + c] = 0;
        Bs[row * 28 + c] = 0;
    }
    __syncthreads();

    float acc[2][4][4];
#pragma unroll
    for (int i = 0; i < 2; i++)
#pragma unroll
        for (int j = 0; j < 4; j++)
#pragma unroll
            for (int k = 0; k < 4; k++) acc[i][j][k] = 0.0f;

#pragma unroll
    for (int kc = 0; kc < 24; kc += 8) {
        uint32_t a[2][4], b[4][2];
#pragma unroll
        for (int ma = 0; ma < 2; ma++) {
            int r = wm * 32 + ma * 16 + gid;
            a[ma][0] = As[r * 28 + kc + tig];
            a[ma][1] = As[(r + 8) * 28 + kc + tig];
            a[ma][2] = As[r * 28 + kc + tig + 4];
            a[ma][3] = As[(r + 8) * 28 + kc + tig + 4];
        }
#pragma unroll
        for (int na = 0; na < 4; na++) {
            int cl = wn * 32 + na * 8 + gid;
            b[na][0] = Bs[cl * 28 + kc + tig];
            b[na][1] = Bs[cl * 28 + kc + tig + 4];
        }
#pragma unroll
        for (int ma = 0; ma < 2; ma++)
#pragma unroll
            for (int na = 0; na < 4; na++)
                mma_tf32(acc[ma][na], a[ma], b[na]);
    }

#pragma unroll
    for (int ma = 0; ma < 2; ma++) {
#pragma unroll
        for (int na = 0; na < 4; na++) {
            int p = p0 + wm * 32 + ma * 16 + gid;
            int n = n0 + wn * 32 + na * 8 + 2 * tig;
            float bx = mvb[n], by = mvb[n + 1];
            float o0 = fcf(acc[ma][na][0] + bx), o1 = fcf(acc[ma][na][1] + by);
            float o2 = fcf(acc[ma][na][2] + bx), o3 = fcf(acc[ma][na][3] + by);
            if (p < E)
                *(__half2*)(g_wh + (size_t)p * 384 + n) = __floats2half2_rn(o0, o1);
            if (p + 8 < E)
                *(__half2*)(g_wh + (size_t)(p + 8) * 384 + n) = __floats2half2_rn(o2, o3);
        }
    }
}

// ---------------- pass 1 consumer: warp per node ----------------------------
__global__ __launch_bounds__(256) void k_pass1(const float* __restrict__ v,
                                               const float* __restrict__ s, int N) {
    int gw = (blockIdx.x * blockDim.x + threadIdx.x) >> 5;
    int lane = threadIdx.x & 31;
    if (gw >= N) return;
    int beg = g_ptr[gw], end = g_ptr[gw + 1];
    float dv[12];
    float ds4[4];
#pragma unroll
    for (int k = 0; k < 12; k++) dv[k] = 0.0f;
#pragma unroll
    for (int k = 0; k < 4; k++) ds4[k] = 0.0f;

#pragma unroll 2
    for (int p = beg; p < end; p++) {
        int sn = g_csr_src[p];
        const __half* ph = g_phih + (size_t)sn * 384;
        int2 t0 = *(const int2*)(ph + 4 * lane);
        int2 t1 = *(const int2*)(ph + 128 + 4 * lane);
        int2 t2 = *(const int2*)(ph + 256 + 4 * lane);
        float2 pv01 = __half22float2(*(__half2*)&t0.x);
        float2 pv23 = __half22float2(*(__half2*)&t0.y);
        float2 ps01 = __half22float2(*(__half2*)&t1.x);
        float2 ps23 = __half22float2(*(__half2*)&t1.y);
        float2 pr01 = __half22float2(*(__half2*)&t2.x);
        float2 pr23 = __half22float2(*(__half2*)&t2.y);
        const __half* wr = g_wh + (size_t)p * 384;
        int2 q0 = *(const int2*)(wr + 4 * lane);
        int2 q1 = *(const int2*)(wr + 128 + 4 * lane);
        int2 q2 = *(const int2*)(wr + 256 + 4 * lane);
        float2 wv01 = __half22float2(*(__half2*)&q0.x);
        float2 wv23 = __half22float2(*(__half2*)&q0.y);
        float2 ws01 = __half22float2(*(__half2*)&q1.x);
        float2 ws23 = __half22float2(*(__half2*)&q1.y);
        float2 wr01 = __half22float2(*(__half2*)&q2.x);
        float2 wr23 = __half22float2(*(__half2*)&q2.y);
        const float4* vrow = (const float4*)(v + (size_t)sn * 384);
        float4 a0 = vrow[3 * lane + 0];
        float4 a1 = vrow[3 * lane + 1];
        float4 a2 = vrow[3 * lane + 2];
        float ux = g_unit[3 * p + 0], uy = g_unit[3 * p + 1], uz = g_unit[3 * p + 2];

        float vv0 = pv01.x * wv01.x, vv1 = pv01.y * wv01.y;
        float vv2 = pv23.x * wv23.x, vv3 = pv23.y * wv23.y;
        float rr0 = pr01.x * wr01.x, rr1 = pr01.y * wr01.y;
        float rr2 = pr23.x * wr23.x, rr3 = pr23.y * wr23.y;
        ds4[0] += ps01.x * ws01.x; ds4[1] += ps01.y * ws01.y;
        ds4[2] += ps23.x * ws23.x; ds4[3] += ps23.y * ws23.y;

        dv[0]  += a0.x * vv0 + rr0 * ux;
        dv[1]  += a0.y * vv0 + rr0 * uy;
        dv[2]  += a0.z * vv0 + rr0 * uz;
        dv[3]  += a0.w * vv1 + rr1 * ux;
        dv[4]  += a1.x * vv1 + rr1 * uy;
        dv[5]  += a1.y * vv1 + rr1 * uz;
        dv[6]  += a1.z * vv2 + rr2 * ux;
        dv[7]  += a1.w * vv2 + rr2 * uy;
        dv[8]  += a2.x * vv2 + rr2 * uz;
        dv[9]  += a2.y * vv3 + rr3 * ux;
        dv[10] += a2.z * vv3 + rr3 * uy;
        dv[11] += a2.w * vv3 + rr3 * uz;
    }
    const float4* vi = (const float4*)(v + (size_t)gw * 384);
    float4 b0 = vi[3 * lane + 0], b1 = vi[3 * lane + 1], b2 = vi[3 * lane + 2];
    b0.x += dv[0]; b0.y += dv[1]; b0.z += dv[2]; b0.w += dv[3];
    b1.x += dv[4]; b1.y += dv[5]; b1.z += dv[6]; b1.w += dv[7];
    b2.x += dv[8]; b2.y += dv[9]; b2.z += dv[10]; b2.w += dv[11];
    float4* vo = (float4*)(g_vnew + (size_t)gw * 384);
    vo[3 * lane + 0] = b0; vo[3 * lane + 1] = b1; vo[3 * lane + 2] = b2;

    // fp16 shadow for pass-2 gathers (12 halves per lane = 3x int2)
    {
        __half* vh = g_vnewh + (size_t)gw * 384 + 12 * lane;
        __half2 h0 = __floats2half2_rn(b0.x, b0.y);
        __half2 h1 = __floats2half2_rn(b0.z, b0.w);
        __half2 h2 = __floats2half2_rn(b1.x, b1.y);
        __half2 h3 = __floats2half2_rn(b1.z, b1.w);
        __half2 h4 = __floats2half2_rn(b2.x, b2.y);
        __half2 h5 = __floats2half2_rn(b2.z, b2.w);
        int2* d = (int2*)vh;
        d[0] = make_int2(*(int*)&h0, *(int*)&h1);
        d[1] = make_int2(*(int*)&h2, *(int*)&h3);
        d[2] = make_int2(*(int*)&h4, *(int*)&h5);
    }

    float4 sv = ((const float4*)(s + (size_t)gw * 128))[lane];
    sv.x += ds4[0]; sv.y += ds4[1]; sv.z += ds4[2]; sv.w += ds4[3];
    ((float4*)(g_snew + (size_t)gw * 128))[lane] = sv;
}

// ---------------- pass 2 consumer + final combine: warp per node -----------
__global__ __launch_bounds__(256) void k_pass2(float* __restrict__ out, int N) {
    int gw = (blockIdx.x * blockDim.x + threadIdx.x) >> 5;
    int lane = threadIdx.x & 31;
    if (gw >= N) return;
    int beg = g_ptr[gw], end = g_ptr[gw + 1];
    int deg = end - beg;

    float uv[12];
    float smv[4], sms[4], smss[4];
#pragma unroll
    for (int k = 0; k < 12; k++) uv[k] = 0.0f;
#pragma unroll
    for (int k = 0; k < 4; k++) { smv[k] = 0.0f; sms[k] = 0.0f; smss[k] = 0.0f; }

#pragma unroll 2
    for (int p = beg; p < end; p++) {
        int sn = g_csr_src[p];
        const __half* vr = g_vnewh + (size_t)sn * 384 + 12 * lane;
        int2 c0 = *(const int2*)(vr);
        int2 c1 = *(const int2*)(vr + 4);
        int2 c2 = *(const int2*)(vr + 8);
        float2 f0 = __half22float2(*(__half2*)&c0.x);
        float2 f1 = __half22float2(*(__half2*)&c0.y);
        float2 f2 = __half22float2(*(__half2*)&c1.x);
        float2 f3 = __half22float2(*(__half2*)&c1.y);
        float2 f4 = __half22float2(*(__half2*)&c2.x);
        float2 f5 = __half22float2(*(__half2*)&c2.y);
        uv[0] += f0.x; uv[1] += f0.y; uv[2]  += f1.x; uv[3]  += f1.y;
        uv[4] += f2.x; uv[5] += f2.y; uv[6]  += f3.x; uv[7]  += f3.y;
        uv[8] += f4.x; uv[9] += f4.y; uv[10] += f5.x; uv[11] += f5.y;

        const __half* sr = g_s2h + (size_t)sn * 384;
        int2 q0 = *(const int2*)(sr + 4 * lane);
        int2 q1 = *(const int2*)(sr + 128 + 4 * lane);
        int2 q2 = *(const int2*)(sr + 256 + 4 * lane);
        float2 m01 = __half22float2(*(__half2*)&q0.x);
        float2 m23 = __half22float2(*(__half2*)&q0.y);
        float2 s01 = __half22float2(*(__half2*)&q1.x);
        float2 s23 = __half22float2(*(__half2*)&q1.y);
        float2 z01 = __half22float2(*(__half2*)&q2.x);
        float2 z23 = __half22float2(*(__half2*)&q2.y);
        smv[0]  += m01.x; smv[1]  += m01.y; smv[2]  += m23.x; smv[3]  += m23.y;
        sms[0]  += s01.x; sms[1]  += s01.y; sms[2]  += s23.x; sms[3]  += s23.y;
        smss[0] += z01.x; smss[1] += z01.y; smss[2] += z23.x; smss[3] += z23.y;
    }
    float inv = 1.0f / fmaxf((float)deg, 1.0f);
#pragma unroll
    for (int k = 0; k < 12; k++) uv[k] *= inv;
    float avv[4], asv[4], ass[4];
#pragma unroll
    for (int j = 0; j < 4; j++) {
        avv[j] = smv[j] * inv;
        asv[j] = sms[j] * inv;
        ass[j] = smss[j] * inv;
    }

    const float4* vi = (const float4*)(g_vnew + (size_t)gw * 384);
    float4 b0 = vi[3 * lane + 0], b1 = vi[3 * lane + 1], b2 = vi[3 * lane + 2];
    b0.x += uv[0] * avv[0]; b0.y += uv[1]  * avv[0]; b0.z += uv[2]  * avv[0];
    b0.w += uv[3] * avv[1]; b1.x += uv[4]  * avv[1]; b1.y += uv[5]  * avv[1];
    b1.z += uv[6] * avv[2]; b1.w += uv[7]  * avv[2]; b2.x += uv[8]  * avv[2];
    b2.y += uv[9] * avv[3]; b2.z += uv[10] * avv[3]; b2.w += uv[11] * avv[3];
    float4* vo = (float4*)(out + (size_t)gw * 384);
    vo[3 * lane + 0] = b0; vo[3 * lane + 1] = b1; vo[3 * lane + 2] = b2;

    float4 sn4 = ((const float4*)(g_snew + (size_t)gw * 128))[lane];
    float so[4];
#pragma unroll
    for (int j = 0; j < 4; j++) {
        float sx = uv[3 * j + 0], sy = uv[3 * j + 1], sz = uv[3 * j + 2];
        float ssq = sx * sx + sy * sy + sz * sz;
        float ratio = ssq / (ssq + 1e-5f);
        so[j] = ratio * asv[j] + ass[j];
    }
    sn4.x += so[0]; sn4.y += so[1]; sn4.z += so[2]; sn4.w += so[3];
    ((float4*)(out + (size_t)N * 384 + (size_t)gw * 128))[lane] = sn4;
}

// ---------------- launcher --------------------------------------------------
extern "C" void kernel_launch(void* const* d_in, const int* in_sizes, int n_in,
                              void* d_out, int out_size) {
    const float* x     = (const float*)d_in[0];
    const float* v     = (const float*)d_in[1];
    const float* s     = (const float*)d_in[2];
    const float* ms1_w = (const float*)d_in[3];
    const float* ms1_b = (const float*)d_in[4];
    const float* ms2_w = (const float*)d_in[5];
    const float* ms2_b = (const float*)d_in[6];
    const float* mv_w  = (const float*)d_in[7];
    const float* mv_b  = (const float*)d_in[8];
    const float* us1_w = (const float*)d_in[9];
    const float* us1_b = (const float*)d_in[10];
    const float* us2_w = (const float*)d_in[11];
    const float* us2_b = (const float*)d_in[12];
    const int*   src   = (const int*)d_in[13];
    const int*   dst   = (const int*)d_in[14];
    float* out = (float*)d_out;

    int N = in_sizes[0] / 3;
    int E = in_sizes[13];

    float *p_h, *p_snew;
    __half *p_phih, *p_s2h;
    int* p_deg;
    cudaGetSymbolAddress((void**)&p_h, g_h);
    cudaGetSymbolAddress((void**)&p_phih, g_phih);
    cudaGetSymbolAddress((void**)&p_snew, g_snew);
    cudaGetSymbolAddress((void**)&p_s2h, g_s2h);
    cudaGetSymbolAddress((void**)&p_deg, g_deg);

    // CSR build
    cudaMemsetAsync(p_deg, 0, (size_t)N * sizeof(int));
    k_hist<<<(E + 255) / 256, 256>>>(dst, E);
    k_scan<<<1, 1024>>>(N);
    k_fill<<<(E + 255) / 256, 256>>>(src, dst, E);

    // per-edge geometry (CSR order)
    k_edge<<<(E + 255) / 256, 256>>>(x, dst, E);

    // pass-1 node MLP (tf32 tensor cores), phi stored fp16
    {
        dim3 ga((N + 63) / 64, 128 / 64);
        k_mlp_tc<1, 0><<<ga, 128>>>(s, ms1_w, ms1_b, p_h, N, 128);
        dim3 gb((N + 63) / 64, 384 / 64);
        k_mlp_tc<0, 1><<<gb, 128>>>(p_h, ms2_w, ms2_b, p_phih, N, 384);
    }

    // per-edge filter weights (tf32 tensor cores, fp16 output)
    {
        dim3 gw_((E + 63) / 64, 384 / 64);
        k_w_tc<<<gw_, 128>>>(mv_w, mv_b, E);
    }

    // pass-1 reduce (warp per node)
    k_pass1<<<(N * 32 + 255) / 256, 256>>>(v, s, N);

    // pass-2 node MLP on s_new (tf32 tensor cores), s2 stored fp16
    {
        dim3 ga((N + 63) / 64, 128 / 64);
        k_mlp_tc<1, 0><<<ga, 128>>>(p_snew, us1_w, us1_b, p_h, N, 128);
        dim3 gb((N + 63) / 64, 384 / 64);
        k_mlp_tc<0, 1><<<gb, 128>>>(p_h, us2_w, us2_b, p_s2h, N, 384);
    }

    // pass-2 reduce + final combine
    k_pass2<<<(N * 32 + 255) / 256, 256>>>(out, N);
}

// round 4
// speedup vs baseline: 1.4979x; 1.0467x over previous
#include <cuda_runtime.h>
#include <cuda_fp16.h>
#include <math.h>
#include <stdint.h>

#define NN 10000
#define EE 100000

// ---------------- scratch (device globals; no allocation allowed) ----------
__device__ float  g_h[NN * 128];       // ssp(s@W1^T+b1) intermediate (fp32)
__device__ __half g_phih[NN * 384];    // pass-1 node MLP output (fp16)
__device__ __half g_vh[NN * 384];      // input v as fp16 (pass-1 gathers)
__device__ float  g_vnew[NN * 384];    // v_new fp32 (own-node reads + precision)
__device__ __half g_vnewh[NN * 384];   // v_new fp16 shadow (pass-2 gathers)
__device__ float  g_snew[NN * 128];    // s_new
__device__ __half g_s2h[NN * 384];     // pass-2 node MLP output (fp16)
__device__ __half g_wh[EE * 384];      // per-edge filter weights, fp16 (CSR order)
__device__ float  g_rbf[EE * 20];      // per-edge radial basis (CSR order)
__device__ float  g_unit[EE * 3];      // per-edge unit vector (CSR order)
__device__ int    g_deg[NN];
__device__ int    g_ptr[NN + 1];
__device__ int    g_fill[NN];
__device__ int    g_csr_src[EE];

// ---------------- helpers ---------------------------------------------------
__device__ __forceinline__ float sspf(float x) {
    float sp = fmaxf(x, 0.0f) + log1pf(expf(-fabsf(x)));
    return sp - 0.69314718055994531f;
}
__device__ __forceinline__ float fcf(float u) {
    return (u < 5.0f) ? 0.5f * (__cosf(0.6283185307179586f * u) + 1.0f) : 0.0f;
}
__device__ __forceinline__ uint32_t f2tf32(float f) {
    uint32_t r;
    asm("cvt.rna.tf32.f32 %0, %1;" : "=r"(r) : "f"(f));
    return r;
}
__device__ __forceinline__ void mma_tf32(float c[4], const uint32_t a[4], const uint32_t b[2]) {
    asm volatile(
        "mma.sync.aligned.m16n8k8.row.col.f32.tf32.tf32.f32 "
        "{%0,%1,%2,%3},{%4,%5,%6,%7},{%8,%9},{%0,%1,%2,%3};"
        : "+f"(c[0]), "+f"(c[1]), "+f"(c[2]), "+f"(c[3])
        : "r"(a[0]), "r"(a[1]), "r"(a[2]), "r"(a[3]), "r"(b[0]), "r"(b[1]));
}

// ---------------- v -> fp16 prologue ----------------------------------------
__global__ void k_vhalf(const float* __restrict__ v, int total) {
    int i = (blockIdx.x * blockDim.x + threadIdx.x) * 8;
    if (i >= total) return;
    float4 a = *(const float4*)(v + i);
    float4 b = *(const float4*)(v + i + 4);
    __half2 h0 = __floats2half2_rn(a.x, a.y);
    __half2 h1 = __floats2half2_rn(a.z, a.w);
    __half2 h2 = __floats2half2_rn(b.x, b.y);
    __half2 h3 = __floats2half2_rn(b.z, b.w);
    int4 o = make_int4(*(int*)&h0, *(int*)&h1, *(int*)&h2, *(int*)&h3);
    *(int4*)(g_vh + i) = o;
}

// ---------------- CSR build -------------------------------------------------
__global__ void k_hist(const int* __restrict__ dst, int E) {
    int e = blockIdx.x * blockDim.x + threadIdx.x;
    if (e < E) atomicAdd(&g_deg[dst[e]], 1);
}

__global__ void k_scan(int N) {
    __shared__ int wsum[32];
    __shared__ int carry_s;
    int t = threadIdx.x, lane = t & 31, wid = t >> 5;
    if (t == 0) carry_s = 0;
    __syncthreads();
    for (int base = 0; base < N; base += 1024) {
        int i = base + t;
        int v = (i < N) ? g_deg[i] : 0;
        int x = v;
#pragma unroll
        for (int o = 1; o < 32; o <<= 1) {
            int y = __shfl_up_sync(0xFFFFFFFFu, x, o);
            if (lane >= o) x += y;
        }
        if (lane == 31) wsum[wid] = x;
        __syncthreads();
        if (wid == 0) {
            int w = wsum[lane];
#pragma unroll
            for (int o = 1; o < 32; o <<= 1) {
                int y = __shfl_up_sync(0xFFFFFFFFu, w, o);
                if (lane >= o) w += y;
            }
            wsum[lane] = w;
        }
        __syncthreads();
        int excl = x - v + (wid ? wsum[wid - 1] : 0) + carry_s;
        if (i < N) {
            g_ptr[i] = excl;
            g_fill[i] = excl;
        }
        int total = wsum[31];
        __syncthreads();
        if (t == 0) carry_s += total;
        __syncthreads();
    }
    if (threadIdx.x == 0) g_ptr[N] = carry_s;
}

// ---------------- fill + per-edge geometry (fused) ---------------------------
__global__ void k_fill_edge(const float* __restrict__ x, const int* __restrict__ src,
                            const int* __restrict__ dst, int E) {
    int e = blockIdx.x * blockDim.x + threadIdx.x;
    if (e >= E) return;
    int d = dst[e];
    int sn = src[e];
    int pos = atomicAdd(&g_fill[d], 1);
    g_csr_src[pos] = sn;

    float vx = x[sn * 3 + 0] - x[d * 3 + 0];
    float vy = x[sn * 3 + 1] - x[d * 3 + 1];
    float vz = x[sn * 3 + 2] - x[d * 3 + 2];
    float r = sqrtf(vx * vx + vy * vy + vz * vz + 1e-5f);
    float inv = 1.0f / r;
    g_unit[pos * 3 + 0] = vx * inv;
    g_unit[pos * 3 + 1] = vy * inv;
    g_unit[pos * 3 + 2] = vz * inv;
    float a = 0.6283185307179586f * r;   // pi*r/5
    float c = 0.6324555320336759f * inv; // sqrt(2/5)/r
    float sa, ca;
    sincosf(a, &sa, &ca);
    float twoc = 2.0f * ca;
    float s_nm1 = 0.0f, s_n = sa;
#pragma unroll
    for (int n = 1; n <= 20; n++) {
        g_rbf[pos * 20 + (n - 1)] = c * s_n;
        float s_np1 = twoc * s_n - s_nm1;
        s_nm1 = s_n;
        s_n = s_np1;
    }
}

// ---------------- tf32 tensor-core node MLP: C = act(A[M,128] @ W[NOUT,128]^T + b)
template <int ACT, int HALF_OUT>
__global__ __launch_bounds__(128) void k_mlp_tc(const float* __restrict__ A,
                                                const float* __restrict__ W,
                                                const float* __restrict__ bias,
                                                void* __restrict__ Cv,
                                                int M, int NOUT) {
    __shared__ uint32_t As[64 * 68];
    __shared__ uint32_t Ws[64 * 68];
    int t = threadIdx.x;
    int warp = t >> 5, lane = t & 31;
    int gid = lane >> 2, tig = lane & 3;
    int wm = warp & 1, wn = warp >> 1;
    int m0 = blockIdx.x * 64, n0 = blockIdx.y * 64;

    float acc[2][4][4];
#pragma unroll
    for (int i = 0; i < 2; i++)
#pragma unroll
        for (int j = 0; j < 4; j++)
#pragma unroll
            for (int k = 0; k < 4; k++) acc[i][j][k] = 0.0f;

    for (int ks = 0; ks < 128; ks += 64) {
        __syncthreads();
        for (int i = t; i < 64 * 16; i += 128) {
            int row = i >> 4, c4 = (i & 15) << 2;
            float4 av = make_float4(0.f, 0.f, 0.f, 0.f);
            if (m0 + row < M)
                av = *(const float4*)(A + (size_t)(m0 + row) * 128 + ks + c4);
            uint32_t* da = &As[row * 68 + c4];
            da[0] = f2tf32(av.x); da[1] = f2tf32(av.y);
            da[2] = f2tf32(av.z); da[3] = f2tf32(av.w);
            float4 wv = *(const float4*)(W + (size_t)(n0 + row) * 128 + ks + c4);
            uint32_t* dw = &Ws[row * 68 + c4];
            dw[0] = f2tf32(wv.x); dw[1] = f2tf32(wv.y);
            dw[2] = f2tf32(wv.z); dw[3] = f2tf32(wv.w);
        }
        __syncthreads();
#pragma unroll
        for (int kc = 0; kc < 64; kc += 8) {
            uint32_t a[2][4], b[4][2];
#pragma unroll
            for (int ma = 0; ma < 2; ma++) {
                int r = wm * 32 + ma * 16 + gid;
                a[ma][0] = As[r * 68 + kc + tig];
                a[ma][1] = As[(r + 8) * 68 + kc + tig];
                a[ma][2] = As[r * 68 + kc + tig + 4];
                a[ma][3] = As[(r + 8) * 68 + kc + tig + 4];
            }
#pragma unroll
            for (int na = 0; na < 4; na++) {
                int cl = wn * 32 + na * 8 + gid;
                b[na][0] = Ws[cl * 68 + kc + tig];
                b[na][1] = Ws[cl * 68 + kc + tig + 4];
            }
#pragma unroll
            for (int ma = 0; ma < 2; ma++)
#pragma unroll
                for (int na = 0; na < 4; na++)
                    mma_tf32(acc[ma][na], a[ma], b[na]);
        }
    }
#pragma unroll
    for (int ma = 0; ma < 2; ma++) {
#pragma unroll
        for (int na = 0; na < 4; na++) {
            int m = m0 + wm * 32 + ma * 16 + gid;
            int n = n0 + wn * 32 + na * 8 + 2 * tig;
            float bx = bias[n], by = bias[n + 1];
            float o0 = acc[ma][na][0] + bx, o1 = acc[ma][na][1] + by;
            float o2 = acc[ma][na][2] + bx, o3 = acc[ma][na][3] + by;
            if (ACT) { o0 = sspf(o0); o1 = sspf(o1); o2 = sspf(o2); o3 = sspf(o3); }
            if (HALF_OUT) {
                __half* C = (__half*)Cv;
                if (m < M) *(__half2*)(C + (size_t)m * NOUT + n) = __floats2half2_rn(o0, o1);
                if (m + 8 < M) *(__half2*)(C + (size_t)(m + 8) * NOUT + n) = __floats2half2_rn(o2, o3);
            } else {
                float* C = (float*)Cv;
                if (m < M) *(float2*)(C + (size_t)m * NOUT + n) = make_float2(o0, o1);
                if (m + 8 < M) *(float2*)(C + (size_t)(m + 8) * NOUT + n) = make_float2(o2, o3);
            }
        }
    }
}

// ---------------- tf32 edge filter GEMM: w = fc(rbf[E,20] @ mv_w[384,20]^T + b)
// One block per 64 edges; loops all 6 output tiles (rbf staged once).
__global__ __launch_bounds__(128) void k_w_tc(const float* __restrict__ mvw,
                                              const float* __restrict__ mvb, int E) {
    __shared__ uint32_t As[64 * 28];
    __shared__ uint32_t Bs[64 * 28];
    int t = threadIdx.x;
    int warp = t >> 5, lane = t & 31;
    int gid = lane >> 2, tig = lane & 3;
    int wm = warp & 1, wn = warp >> 1;
    int p0 = blockIdx.x * 64;

    // stage rbf once; zero pads of both tiles
    for (int i = t; i < 64 * 20; i += 128) {
        int row = i / 20, c = i - row * 20;
        float av = (p0 + row < E) ? g_rbf[(size_t)(p0 + row) * 20 + c] : 0.0f;
        As[row * 28 + c] = f2tf32(av);
    }
    for (int i = t; i < 64 * 8; i += 128) {
        int row = i >> 3, c = 20 + (i & 7);
        As[row * 28 + c] = 0;
        Bs[row * 28 + c] = 0;
    }

    for (int n0 = 0; n0 < 384; n0 += 64) {
        __syncthreads();
        for (int i = t; i < 64 * 20; i += 128) {
            int row = i / 20, c = i - row * 20;
            Bs[row * 28 + c] = f2tf32(mvw[(size_t)(n0 + row) * 20 + c]);
        }
        __syncthreads();

        float acc[2][4][4];
#pragma unroll
        for (int i = 0; i < 2; i++)
#pragma unroll
            for (int j = 0; j < 4; j++)
#pragma unroll
                for (int k = 0; k < 4; k++) acc[i][j][k] = 0.0f;

#pragma unroll
        for (int kc = 0; kc < 24; kc += 8) {
            uint32_t a[2][4], b[4][2];
#pragma unroll
            for (int ma = 0; ma < 2; ma++) {
                int r = wm * 32 + ma * 16 + gid;
                a[ma][0] = As[r * 28 + kc + tig];
                a[ma][1] = As[(r + 8) * 28 + kc + tig];
                a[ma][2] = As[r * 28 + kc + tig + 4];
                a[ma][3] = As[(r + 8) * 28 + kc + tig + 4];
            }
#pragma unroll
            for (int na = 0; na < 4; na++) {
                int cl = wn * 32 + na * 8 + gid;
                b[na][0] = Bs[cl * 28 + kc + tig];
                b[na][1] = Bs[cl * 28 + kc + tig + 4];
            }
#pragma unroll
            for (int ma = 0; ma < 2; ma++)
#pragma unroll
                for (int na = 0; na < 4; na++)
                    mma_tf32(acc[ma][na], a[ma], b[na]);
        }

#pragma unroll
        for (int ma = 0; ma < 2; ma++) {
#pragma unroll
            for (int na = 0; na < 4; na++) {
                int p = p0 + wm * 32 + ma * 16 + gid;
                int n = n0 + wn * 32 + na * 8 + 2 * tig;
                float bx = mvb[n], by = mvb[n + 1];
                float o0 = fcf(acc[ma][na][0] + bx), o1 = fcf(acc[ma][na][1] + by);
                float o2 = fcf(acc[ma][na][2] + bx), o3 = fcf(acc[ma][na][3] + by);
                if (p < E)
                    *(__half2*)(g_wh + (size_t)p * 384 + n) = __floats2half2_rn(o0, o1);
                if (p + 8 < E)
                    *(__half2*)(g_wh + (size_t)(p + 8) * 384 + n) = __floats2half2_rn(o2, o3);
            }
        }
    }
}

// ---------------- pass 1 consumer: warp per node ----------------------------
__global__ __launch_bounds__(256) void k_pass1(const float* __restrict__ v,
                                               const float* __restrict__ s, int N) {
    int gw = (blockIdx.x * blockDim.x + threadIdx.x) >> 5;
    int lane = threadIdx.x & 31;
    if (gw >= N) return;
    int beg = g_ptr[gw], end = g_ptr[gw + 1];
    float dv[12];
    float ds4[4];
#pragma unroll
    for (int k = 0; k < 12; k++) dv[k] = 0.0f;
#pragma unroll
    for (int k = 0; k < 4; k++) ds4[k] = 0.0f;

#pragma unroll 2
    for (int p = beg; p < end; p++) {
        int sn = g_csr_src[p];
        const __half* ph = g_phih + (size_t)sn * 384;
        int2 t0 = *(const int2*)(ph + 4 * lane);
        int2 t1 = *(const int2*)(ph + 128 + 4 * lane);
        int2 t2 = *(const int2*)(ph + 256 + 4 * lane);
        float2 pv01 = __half22float2(*(__half2*)&t0.x);
        float2 pv23 = __half22float2(*(__half2*)&t0.y);
        float2 ps01 = __half22float2(*(__half2*)&t1.x);
        float2 ps23 = __half22float2(*(__half2*)&t1.y);
        float2 pr01 = __half22float2(*(__half2*)&t2.x);
        float2 pr23 = __half22float2(*(__half2*)&t2.y);
        const __half* wr = g_wh + (size_t)p * 384;
        int2 q0 = *(const int2*)(wr + 4 * lane);
        int2 q1 = *(const int2*)(wr + 128 + 4 * lane);
        int2 q2 = *(const int2*)(wr + 256 + 4 * lane);
        float2 wv01 = __half22float2(*(__half2*)&q0.x);
        float2 wv23 = __half22float2(*(__half2*)&q0.y);
        float2 ws01 = __half22float2(*(__half2*)&q1.x);
        float2 ws23 = __half22float2(*(__half2*)&q1.y);
        float2 wr01 = __half22float2(*(__half2*)&q2.x);
        float2 wr23 = __half22float2(*(__half2*)&q2.y);
        const __half* vr = g_vh + (size_t)sn * 384 + 12 * lane;
        int2 c0 = *(const int2*)(vr);
        int2 c1 = *(const int2*)(vr + 4);
        int2 c2 = *(const int2*)(vr + 8);
        float2 f0 = __half22float2(*(__half2*)&c0.x);
        float2 f1 = __half22float2(*(__half2*)&c0.y);
        float2 f2 = __half22float2(*(__half2*)&c1.x);
        float2 f3 = __half22float2(*(__half2*)&c1.y);
        float2 f4 = __half22float2(*(__half2*)&c2.x);
        float2 f5 = __half22float2(*(__half2*)&c2.y);
        float ux = g_unit[3 * p + 0], uy = g_unit[3 * p + 1], uz = g_unit[3 * p + 2];

        float vv0 = pv01.x * wv01.x, vv1 = pv01.y * wv01.y;
        float vv2 = pv23.x * wv23.x, vv3 = pv23.y * wv23.y;
        float rr0 = pr01.x * wr01.x, rr1 = pr01.y * wr01.y;
        float rr2 = pr23.x * wr23.x, rr3 = pr23.y * wr23.y;
        ds4[0] += ps01.x * ws01.x; ds4[1] += ps01.y * ws01.y;
        ds4[2] += ps23.x * ws23.x; ds4[3] += ps23.y * ws23.y;

        dv[0]  += f0.x * vv0 + rr0 * ux;
        dv[1]  += f0.y * vv0 + rr0 * uy;
        dv[2]  += f1.x * vv0 + rr0 * uz;
        dv[3]  += f1.y * vv1 + rr1 * ux;
        dv[4]  += f2.x * vv1 + rr1 * uy;
        dv[5]  += f2.y * vv1 + rr1 * uz;
        dv[6]  += f3.x * vv2 + rr2 * ux;
        dv[7]  += f3.y * vv2 + rr2 * uy;
        dv[8]  += f4.x * vv2 + rr2 * uz;
        dv[9]  += f4.y * vv3 + rr3 * ux;
        dv[10] += f5.x * vv3 + rr3 * uy;
        dv[11] += f5.y * vv3 + rr3 * uz;
    }
    const float4* vi = (const float4*)(v + (size_t)gw * 384);
    float4 b0 = vi[3 * lane + 0], b1 = vi[3 * lane + 1], b2 = vi[3 * lane + 2];
    b0.x += dv[0]; b0.y += dv[1]; b0.z += dv[2]; b0.w += dv[3];
    b1.x += dv[4]; b1.y += dv[5]; b1.z += dv[6]; b1.w += dv[7];
    b2.x += dv[8]; b2.y += dv[9]; b2.z += dv[10]; b2.w += dv[11];
    float4* vo = (float4*)(g_vnew + (size_t)gw * 384);
    vo[3 * lane + 0] = b0; vo[3 * lane + 1] = b1; vo[3 * lane + 2] = b2;

    {
        __half* vh = g_vnewh + (size_t)gw * 384 + 12 * lane;
        __half2 h0 = __floats2half2_rn(b0.x, b0.y);
        __half2 h1 = __floats2half2_rn(b0.z, b0.w);
        __half2 h2 = __floats2half2_rn(b1.x, b1.y);
        __half2 h3 = __floats2half2_rn(b1.z, b1.w);
        __half2 h4 = __floats2half2_rn(b2.x, b2.y);
        __half2 h5 = __floats2half2_rn(b2.z, b2.w);
        int2* d = (int2*)vh;
        d[0] = make_int2(*(int*)&h0, *(int*)&h1);
        d[1] = make_int2(*(int*)&h2, *(int*)&h3);
        d[2] = make_int2(*(int*)&h4, *(int*)&h5);
    }

    float4 sv = ((const float4*)(s + (size_t)gw * 128))[lane];
    sv.x += ds4[0]; sv.y += ds4[1]; sv.z += ds4[2]; sv.w += ds4[3];
    ((float4*)(g_snew + (size_t)gw * 128))[lane] = sv;
}

// ---------------- pass 2 consumer + final combine: warp per node -----------
__global__ __launch_bounds__(256) void k_pass2(float* __restrict__ out, int N) {
    int gw = (blockIdx.x * blockDim.x + threadIdx.x) >> 5;
    int lane = threadIdx.x & 31;
    if (gw >= N) return;
    int beg = g_ptr[gw], end = g_ptr[gw + 1];
    int deg = end - beg;

    float uv[12];
    float smv[4], sms[4], smss[4];
#pragma unroll
    for (int k = 0; k < 12; k++) uv[k] = 0.0f;
#pragma unroll
    for (int k = 0; k < 4; k++) { smv[k] = 0.0f; sms[k] = 0.0f; smss[k] = 0.0f; }

#pragma unroll 2
    for (int p = beg; p < end; p++) {
        int sn = g_csr_src[p];
        const __half* vr = g_vnewh + (size_t)sn * 384 + 12 * lane;
        int2 c0 = *(const int2*)(vr);
        int2 c1 = *(const int2*)(vr + 4);
        int2 c2 = *(const int2*)(vr + 8);
        float2 f0 = __half22float2(*(__half2*)&c0.x);
        float2 f1 = __half22float2(*(__half2*)&c0.y);
        float2 f2 = __half22float2(*(__half2*)&c1.x);
        float2 f3 = __half22float2(*(__half2*)&c1.y);
        float2 f4 = __half22float2(*(__half2*)&c2.x);
        float2 f5 = __half22float2(*(__half2*)&c2.y);
        uv[0] += f0.x; uv[1] += f0.y; uv[2]  += f1.x; uv[3]  += f1.y;
        uv[4] += f2.x; uv[5] += f2.y; uv[6]  += f3.x; uv[7]  += f3.y;
        uv[8] += f4.x; uv[9] += f4.y; uv[10] += f5.x; uv[11] += f5.y;

        const __half* sr = g_s2h + (size_t)sn * 384;
        int2 q0 = *(const int2*)(sr + 4 * lane);
        int2 q1 = *(const int2*)(sr + 128 + 4 * lane);
        int2 q2 = *(const int2*)(sr + 256 + 4 * lane);
        float2 m01 = __half22float2(*(__half2*)&q0.x);
        float2 m23 = __half22float2(*(__half2*)&q0.y);
        float2 s01 = __half22float2(*(__half2*)&q1.x);
        float2 s23 = __half22float2(*(__half2*)&q1.y);
        float2 z01 = __half22float2(*(__half2*)&q2.x);
        float2 z23 = __half22float2(*(__half2*)&q2.y);
        smv[0]  += m01.x; smv[1]  += m01.y; smv[2]  += m23.x; smv[3]  += m23.y;
        sms[0]  += s01.x; sms[1]  += s01.y; sms[2]  += s23.x; sms[3]  += s23.y;
        smss[0] += z01.x; smss[1] += z01.y; smss[2] += z23.x; smss[3] += z23.y;
    }
    float inv = 1.0f / fmaxf((float)deg, 1.0f);
#pragma unroll
    for (int k = 0; k < 12; k++) uv[k] *= inv;
    float avv[4], asv[4], ass[4];
#pragma unroll
    for (int j = 0; j < 4; j++) {
        avv[j] = smv[j] * inv;
        asv[j] = sms[j] * inv;
        ass[j] = smss[j] * inv;
    }

    const float4* vi = (const float4*)(g_vnew + (size_t)gw * 384);
    float4 b0 = vi[3 * lane + 0], b1 = vi[3 * lane + 1], b2 = vi[3 * lane + 2];
    b0.x += uv[0] * avv[0]; b0.y += uv[1]  * avv[0]; b0.z += uv[2]  * avv[0];
    b0.w += uv[3] * avv[1]; b1.x += uv[4]  * avv[1]; b1.y += uv[5]  * avv[1];
    b1.z += uv[6] * avv[2]; b1.w += uv[7]  * avv[2]; b2.x += uv[8]  * avv[2];
    b2.y += uv[9] * avv[3]; b2.z += uv[10] * avv[3]; b2.w += uv[11] * avv[3];
    float4* vo = (float4*)(out + (size_t)gw * 384);
    vo[3 * lane + 0] = b0; vo[3 * lane + 1] = b1; vo[3 * lane + 2] = b2;

    float4 sn4 = ((const float4*)(g_snew + (size_t)gw * 128))[lane];
    float so[4];
#pragma unroll
    for (int j = 0; j < 4; j++) {
        float sx = uv[3 * j + 0], sy = uv[3 * j + 1], sz = uv[3 * j + 2];
        float ssq = sx * sx + sy * sy + sz * sz;
        float ratio = ssq / (ssq + 1e-5f);
        so[j] = ratio * asv[j] + ass[j];
    }
    sn4.x += so[0]; sn4.y += so[1]; sn4.z += so[2]; sn4.w += so[3];
    ((float4*)(out + (size_t)N * 384 + (size_t)gw * 128))[lane] = sn4;
}

// ---------------- launcher --------------------------------------------------
extern "C" void kernel_launch(void* const* d_in, const int* in_sizes, int n_in,
                              void* d_out, int out_size) {
    const float* x     = (const float*)d_in[0];
    const float* v     = (const float*)d_in[1];
    const float* s     = (const float*)d_in[2];
    const float* ms1_w = (const float*)d_in[3];
    const float* ms1_b = (const float*)d_in[4];
    const float* ms2_w = (const float*)d_in[5];
    const float* ms2_b = (const float*)d_in[6];
    const float* mv_w  = (const float*)d_in[7];
    const float* mv_b  = (const float*)d_in[8];
    const float* us1_w = (const float*)d_in[9];
    const float* us1_b = (const float*)d_in[10];
    const float* us2_w = (const float*)d_in[11];
    const float* us2_b = (const float*)d_in[12];
    const int*   src   = (const int*)d_in[13];
    const int*   dst   = (const int*)d_in[14];
    float* out = (float*)d_out;

    int N = in_sizes[0] / 3;
    int E = in_sizes[13];

    float *p_h, *p_snew;
    __half *p_phih, *p_s2h;
    int* p_deg;
    cudaGetSymbolAddress((void**)&p_h, g_h);
    cudaGetSymbolAddress((void**)&p_phih, g_phih);
    cudaGetSymbolAddress((void**)&p_snew, g_snew);
    cudaGetSymbolAddress((void**)&p_s2h, g_s2h);
    cudaGetSymbolAddress((void**)&p_deg, g_deg);

    // CSR build (+ fused per-edge geometry)
    cudaMemsetAsync(p_deg, 0, (size_t)N * sizeof(int));
    k_hist<<<(E + 255) / 256, 256>>>(dst, E);
    k_scan<<<1, 1024>>>(N);
    k_fill_edge<<<(E + 255) / 256, 256>>>(x, src, dst, E);

    // v -> fp16 copy for pass-1 gathers
    k_vhalf<<<(N * 384 / 8 + 255) / 256, 256>>>(v, N * 384);

    // pass-1 node MLP (tf32 tensor cores), phi stored fp16
    {
        dim3 ga((N + 63) / 64, 128 / 64);
        k_mlp_tc<1, 0><<<ga, 128>>>(s, ms1_w, ms1_b, p_h, N, 128);
        dim3 gb((N + 63) / 64, 384 / 64);
        k_mlp_tc<0, 1><<<gb, 128>>>(p_h, ms2_w, ms2_b, p_phih, N, 384);
    }

    // per-edge filter weights (tf32 tensor cores, fp16 output, rbf staged once)
    k_w_tc<<<(E + 63) / 64, 128>>>(mv_w, mv_b, E);

    // pass-1 reduce (warp per node)
    k_pass1<<<(N * 32 + 255) / 256, 256>>>(v, s, N);

    // pass-2 node MLP on s_new (tf32 tensor cores), s2 stored fp16
    {
        dim3 ga((N + 63) / 64, 128 / 64);
        k_mlp_tc<1, 0><<<ga, 128>>>(p_snew, us1_w, us1_b, p_h, N, 128);
        dim3 gb((N + 63) / 64, 384 / 64);
        k_mlp_tc<0, 1><<<gb, 128>>>(p_h, us2_w, us2_b, p_s2h, N, 384);
    }

    // pass-2 reduce + final combine
    k_pass2<<<(N * 32 + 255) / 256, 256>>>(out, N);
}

// round 5
// speedup vs baseline: 1.9963x; 1.3327x over previous
#include <cuda_runtime.h>
#include <cuda_fp16.h>
#include <math.h>
#include <stdint.h>

#define NN 10000
#define EE 100000
#define TBL 8192
#define TBL_RMAX 25.0f

// ---------------- scratch (device globals; no allocation allowed) ----------
__device__ float  g_h[NN * 128];       // ssp(s@W1^T+b1) intermediate (fp32)
__device__ __half g_phih[NN * 384];    // pass-1 node MLP output (fp16)
__device__ __half g_vh[NN * 384];      // input v as fp16 (pass-1 gathers)
__device__ float  g_vnew[NN * 384];    // v_new fp32 (own-node reads + precision)
__device__ __half g_vnewh[NN * 384];   // v_new fp16 shadow (pass-2 gathers)
__device__ float  g_snew[NN * 128];    // s_new
__device__ __half g_s2h[NN * 384];     // pass-2 node MLP output (fp16)
__device__ __half g_wt[TBL * 384];     // filter weight lookup table over r (fp16)
__device__ float4 g_geo[EE];           // per-edge {unit.xyz, r} (CSR order)
__device__ int    g_deg[NN];
__device__ int    g_ptr[NN + 1];
__device__ int    g_fill[NN];
__device__ int    g_csr_src[EE];

// ---------------- helpers ---------------------------------------------------
__device__ __forceinline__ float sspf(float x) {
    float sp = fmaxf(x, 0.0f) + log1pf(expf(-fabsf(x)));
    return sp - 0.69314718055994531f;
}
__device__ __forceinline__ float fcf(float u) {
    return (u < 5.0f) ? 0.5f * (__cosf(0.6283185307179586f * u) + 1.0f) : 0.0f;
}
__device__ __forceinline__ uint32_t f2tf32(float f) {
    uint32_t r;
    asm("cvt.rna.tf32.f32 %0, %1;" : "=r"(r) : "f"(f));
    return r;
}
__device__ __forceinline__ void mma_tf32(float c[4], const uint32_t a[4], const uint32_t b[2]) {
    asm volatile(
        "mma.sync.aligned.m16n8k8.row.col.f32.tf32.tf32.f32 "
        "{%0,%1,%2,%3},{%4,%5,%6,%7},{%8,%9},{%0,%1,%2,%3};"
        : "+f"(c[0]), "+f"(c[1]), "+f"(c[2]), "+f"(c[3])
        : "r"(a[0]), "r"(a[1]), "r"(a[2]), "r"(a[3]), "r"(b[0]), "r"(b[1]));
}

// ---------------- combined: histogram + v->fp16 ------------------------------
__global__ void k_hist_vhalf(const int* __restrict__ dst, const float* __restrict__ v,
                             int E, int total, int histBlocks) {
    int b = blockIdx.x;
    if (b < histBlocks) {
        int e = b * 256 + threadIdx.x;
        if (e < E) atomicAdd(&g_deg[dst[e]], 1);
    } else {
        int i = ((b - histBlocks) * 256 + threadIdx.x) * 8;
        if (i >= total) return;
        float4 a = *(const float4*)(v + i);
        float4 c = *(const float4*)(v + i + 4);
        __half2 h0 = __floats2half2_rn(a.x, a.y);
        __half2 h1 = __floats2half2_rn(a.z, a.w);
        __half2 h2 = __floats2half2_rn(c.x, c.y);
        __half2 h3 = __floats2half2_rn(c.z, c.w);
        int4 o = make_int4(*(int*)&h0, *(int*)&h1, *(int*)&h2, *(int*)&h3);
        *(int4*)(g_vh + i) = o;
    }
}

// ---------------- prefix scan ------------------------------------------------
__global__ void k_scan(int N) {
    __shared__ int wsum[32];
    __shared__ int carry_s;
    int t = threadIdx.x, lane = t & 31, wid = t >> 5;
    if (t == 0) carry_s = 0;
    __syncthreads();
    for (int base = 0; base < N; base += 1024) {
        int i = base + t;
        int v = (i < N) ? g_deg[i] : 0;
        int x = v;
#pragma unroll
        for (int o = 1; o < 32; o <<= 1) {
            int y = __shfl_up_sync(0xFFFFFFFFu, x, o);
            if (lane >= o) x += y;
        }
        if (lane == 31) wsum[wid] = x;
        __syncthreads();
        if (wid == 0) {
            int w = wsum[lane];
#pragma unroll
            for (int o = 1; o < 32; o <<= 1) {
                int y = __shfl_up_sync(0xFFFFFFFFu, w, o);
                if (lane >= o) w += y;
            }
            wsum[lane] = w;
        }
        __syncthreads();
        int excl = x - v + (wid ? wsum[wid - 1] : 0) + carry_s;
        if (i < N) {
            g_ptr[i] = excl;
            g_fill[i] = excl;
        }
        int total = wsum[31];
        __syncthreads();
        if (t == 0) carry_s += total;
        __syncthreads();
    }
    if (threadIdx.x == 0) g_ptr[N] = carry_s;
}

// ---------------- fill + per-edge geometry (fused, no rbf) -------------------
__global__ void k_fill_edge(const float* __restrict__ x, const int* __restrict__ src,
                            const int* __restrict__ dst, int E) {
    int e = blockIdx.x * blockDim.x + threadIdx.x;
    if (e >= E) return;
    int d = dst[e];
    int sn = src[e];
    int pos = atomicAdd(&g_fill[d], 1);
    g_csr_src[pos] = sn;

    float vx = x[sn * 3 + 0] - x[d * 3 + 0];
    float vy = x[sn * 3 + 1] - x[d * 3 + 1];
    float vz = x[sn * 3 + 2] - x[d * 3 + 2];
    float r = sqrtf(vx * vx + vy * vy + vz * vz + 1e-5f);
    float inv = 1.0f / r;
    g_geo[pos] = make_float4(vx * inv, vy * inv, vz * inv, r);
}

// ---------------- filter weight table build: w(r) = fc(rbf(r)@mv_w^T + b) ----
// 128 blocks x 64 table rows, tf32 mma, loops 6 output tiles.
__global__ __launch_bounds__(128) void k_wtab(const float* __restrict__ mvw,
                                              const float* __restrict__ mvb) {
    __shared__ uint32_t As[64 * 28];
    __shared__ uint32_t Bs[64 * 28];
    int t = threadIdx.x;
    int warp = t >> 5, lane = t & 31;
    int gid = lane >> 2, tig = lane & 3;
    int wm = warp & 1, wn = warp >> 1;
    int p0 = blockIdx.x * 64;
    const float dR = TBL_RMAX / (float)TBL;

    // compute rbf rows directly for the 64 r values
    for (int i = t; i < 64 * 20; i += 128) {
        int row = i / 20, n = i - row * 20 + 1;
        float r = fmaxf((float)(p0 + row) * dR, 1e-4f);
        float val = (0.6324555320336759f / r) * sinf(0.6283185307179586f * r * (float)n);
        As[row * 28 + (n - 1)] = f2tf32(val);
    }
    for (int i = t; i < 64 * 8; i += 128) {
        int row = i >> 3, c = 20 + (i & 7);
        As[row * 28 + c] = 0;
        Bs[row * 28 + c] = 0;
    }

    for (int n0 = 0; n0 < 384; n0 += 64) {
        __syncthreads();
        for (int i = t; i < 64 * 20; i += 128) {
            int row = i / 20, c = i - row * 20;
            Bs[row * 28 + c] = f2tf32(mvw[(size_t)(n0 + row) * 20 + c]);
        }
        __syncthreads();

        float acc[2][4][4];
#pragma unroll
        for (int i = 0; i < 2; i++)
#pragma unroll
            for (int j = 0; j < 4; j++)
#pragma unroll
                for (int k = 0; k < 4; k++) acc[i][j][k] = 0.0f;

#pragma unroll
        for (int kc = 0; kc < 24; kc += 8) {
            uint32_t a[2][4], b[4][2];
#pragma unroll
            for (int ma = 0; ma < 2; ma++) {
                int r = wm * 32 + ma * 16 + gid;
                a[ma][0] = As[r * 28 + kc + tig];
                a[ma][1] = As[(r + 8) * 28 + kc + tig];
                a[ma][2] = As[r * 28 + kc + tig + 4];
                a[ma][3] = As[(r + 8) * 28 + kc + tig + 4];
            }
#pragma unroll
            for (int na = 0; na < 4; na++) {
                int cl = wn * 32 + na * 8 + gid;
                b[na][0] = Bs[cl * 28 + kc + tig];
                b[na][1] = Bs[cl * 28 + kc + tig + 4];
            }
#pragma unroll
            for (int ma = 0; ma < 2; ma++)
#pragma unroll
                for (int na = 0; na < 4; na++)
                    mma_tf32(acc[ma][na], a[ma], b[na]);
        }

#pragma unroll
        for (int ma = 0; ma < 2; ma++) {
#pragma unroll
            for (int na = 0; na < 4; na++) {
                int p = p0 + wm * 32 + ma * 16 + gid;
                int n = n0 + wn * 32 + na * 8 + 2 * tig;
                float bx = mvb[n], by = mvb[n + 1];
                float o0 = fcf(acc[ma][na][0] + bx), o1 = fcf(acc[ma][na][1] + by);
                float o2 = fcf(acc[ma][na][2] + bx), o3 = fcf(acc[ma][na][3] + by);
                *(__half2*)(g_wt + (size_t)p * 384 + n) = __floats2half2_rn(o0, o1);
                *(__half2*)(g_wt + (size_t)(p + 8) * 384 + n) = __floats2half2_rn(o2, o3);
            }
        }
    }
}

// ---------------- tf32 tensor-core node MLP: C = act(A[M,128] @ W[NOUT,128]^T + b)
template <int ACT, int HALF_OUT>
__global__ __launch_bounds__(128) void k_mlp_tc(const float* __restrict__ A,
                                                const float* __restrict__ W,
                                                const float* __restrict__ bias,
                                                void* __restrict__ Cv,
                                                int M, int NOUT) {
    __shared__ uint32_t As[64 * 68];
    __shared__ uint32_t Ws[64 * 68];
    int t = threadIdx.x;
    int warp = t >> 5, lane = t & 31;
    int gid = lane >> 2, tig = lane & 3;
    int wm = warp & 1, wn = warp >> 1;
    int m0 = blockIdx.x * 64, n0 = blockIdx.y * 64;

    float acc[2][4][4];
#pragma unroll
    for (int i = 0; i < 2; i++)
#pragma unroll
        for (int j = 0; j < 4; j++)
#pragma unroll
            for (int k = 0; k < 4; k++) acc[i][j][k] = 0.0f;

    for (int ks = 0; ks < 128; ks += 64) {
        __syncthreads();
        for (int i = t; i < 64 * 16; i += 128) {
            int row = i >> 4, c4 = (i & 15) << 2;
            float4 av = make_float4(0.f, 0.f, 0.f, 0.f);
            if (m0 + row < M)
                av = *(const float4*)(A + (size_t)(m0 + row) * 128 + ks + c4);
            uint32_t* da = &As[row * 68 + c4];
            da[0] = f2tf32(av.x); da[1] = f2tf32(av.y);
            da[2] = f2tf32(av.z); da[3] = f2tf32(av.w);
            float4 wv = *(const float4*)(W + (size_t)(n0 + row) * 128 + ks + c4);
            uint32_t* dw = &Ws[row * 68 + c4];
            dw[0] = f2tf32(wv.x); dw[1] = f2tf32(wv.y);
            dw[2] = f2tf32(wv.z); dw[3] = f2tf32(wv.w);
        }
        __syncthreads();
#pragma unroll
        for (int kc = 0; kc < 64; kc += 8) {
            uint32_t a[2][4], b[4][2];
#pragma unroll
            for (int ma = 0; ma < 2; ma++) {
                int r = wm * 32 + ma * 16 + gid;
                a[ma][0] = As[r * 68 + kc + tig];
                a[ma][1] = As[(r + 8) * 68 + kc + tig];
                a[ma][2] = As[r * 68 + kc + tig + 4];
                a[ma][3] = As[(r + 8) * 68 + kc + tig + 4];
            }
#pragma unroll
            for (int na = 0; na < 4; na++) {
                int cl = wn * 32 + na * 8 + gid;
                b[na][0] = Ws[cl * 68 + kc + tig];
                b[na][1] = Ws[cl * 68 + kc + tig + 4];
            }
#pragma unroll
            for (int ma = 0; ma < 2; ma++)
#pragma unroll
                for (int na = 0; na < 4; na++)
                    mma_tf32(acc[ma][na], a[ma], b[na]);
        }
    }
#pragma unroll
    for (int ma = 0; ma < 2; ma++) {
#pragma unroll
        for (int na = 0; na < 4; na++) {
            int m = m0 + wm * 32 + ma * 16 + gid;
            int n = n0 + wn * 32 + na * 8 + 2 * tig;
            float bx = bias[n], by = bias[n + 1];
            float o0 = acc[ma][na][0] + bx, o1 = acc[ma][na][1] + by;
            float o2 = acc[ma][na][2] + bx, o3 = acc[ma][na][3] + by;
            if (ACT) { o0 = sspf(o0); o1 = sspf(o1); o2 = sspf(o2); o3 = sspf(o3); }
            if (HALF_OUT) {
                __half* C = (__half*)Cv;
                if (m < M) *(__half2*)(C + (size_t)m * NOUT + n) = __floats2half2_rn(o0, o1);
                if (m + 8 < M) *(__half2*)(C + (size_t)(m + 8) * NOUT + n) = __floats2half2_rn(o2, o3);
            } else {
                float* C = (float*)Cv;
                if (m < M) *(float2*)(C + (size_t)m * NOUT + n) = make_float2(o0, o1);
                if (m + 8 < M) *(float2*)(C + (size_t)(m + 8) * NOUT + n) = make_float2(o2, o3);
            }
        }
    }
}

// ---------------- pass 1 consumer: warp per node, table-interpolated w -------
__global__ __launch_bounds__(256) void k_pass1(const float* __restrict__ v,
                                               const float* __restrict__ s, int N) {
    int gw = (blockIdx.x * blockDim.x + threadIdx.x) >> 5;
    int lane = threadIdx.x & 31;
    if (gw >= N) return;
    int beg = g_ptr[gw], end = g_ptr[gw + 1];
    float dv[12];
    float ds4[4];
#pragma unroll
    for (int k = 0; k < 12; k++) dv[k] = 0.0f;
#pragma unroll
    for (int k = 0; k < 4; k++) ds4[k] = 0.0f;

    const float invDR = (float)TBL / TBL_RMAX;

#pragma unroll 2
    for (int p = beg; p < end; p++) {
        int sn = g_csr_src[p];
        float4 geo = g_geo[p];   // uniform across warp (broadcast)
        float rt = fminf(geo.w * invDR, (float)TBL - 1.001f);
        int i0 = (int)rt;
        float fr = rt - (float)i0;

        const __half* ph = g_phih + (size_t)sn * 384;
        int2 t0 = *(const int2*)(ph + 4 * lane);
        int2 t1 = *(const int2*)(ph + 128 + 4 * lane);
        int2 t2 = *(const int2*)(ph + 256 + 4 * lane);
        float2 pv01 = __half22float2(*(__half2*)&t0.x);
        float2 pv23 = __half22float2(*(__half2*)&t0.y);
        float2 ps01 = __half22float2(*(__half2*)&t1.x);
        float2 ps23 = __half22float2(*(__half2*)&t1.y);
        float2 pr01 = __half22float2(*(__half2*)&t2.x);
        float2 pr23 = __half22float2(*(__half2*)&t2.y);

        const __half* wl = g_wt + (size_t)i0 * 384;
        int2 a0l = *(const int2*)(wl + 4 * lane);
        int2 a1l = *(const int2*)(wl + 128 + 4 * lane);
        int2 a2l = *(const int2*)(wl + 256 + 4 * lane);
        const __half* wh = wl + 384;
        int2 a0h = *(const int2*)(wh + 4 * lane);
        int2 a1h = *(const int2*)(wh + 128 + 4 * lane);
        int2 a2h = *(const int2*)(wh + 256 + 4 * lane);

        float2 l0 = __half22float2(*(__half2*)&a0l.x);
        float2 l1 = __half22float2(*(__half2*)&a0l.y);
        float2 h0 = __half22float2(*(__half2*)&a0h.x);
        float2 h1 = __half22float2(*(__half2*)&a0h.y);
        float wv0 = l0.x + fr * (h0.x - l0.x);
        float wv1 = l0.y + fr * (h0.y - l0.y);
        float wv2 = l1.x + fr * (h1.x - l1.x);
        float wv3 = l1.y + fr * (h1.y - l1.y);

        float2 sl0 = __half22float2(*(__half2*)&a1l.x);
        float2 sl1 = __half22float2(*(__half2*)&a1l.y);
        float2 sh0 = __half22float2(*(__half2*)&a1h.x);
        float2 sh1 = __half22float2(*(__half2*)&a1h.y);
        float ws0 = sl0.x + fr * (sh0.x - sl0.x);
        float ws1 = sl0.y + fr * (sh0.y - sl0.y);
        float ws2 = sl1.x + fr * (sh1.x - sl1.x);
        float ws3 = sl1.y + fr * (sh1.y - sl1.y);

        float2 rl0 = __half22float2(*(__half2*)&a2l.x);
        float2 rl1 = __half22float2(*(__half2*)&a2l.y);
        float2 rh0 = __half22float2(*(__half2*)&a2h.x);
        float2 rh1 = __half22float2(*(__half2*)&a2h.y);
        float wr0 = rl0.x + fr * (rh0.x - rl0.x);
        float wr1 = rl0.y + fr * (rh0.y - rl0.y);
        float wr2 = rl1.x + fr * (rh1.x - rl1.x);
        float wr3 = rl1.y + fr * (rh1.y - rl1.y);

        const __half* vr = g_vh + (size_t)sn * 384 + 12 * lane;
        int2 c0 = *(const int2*)(vr);
        int2 c1 = *(const int2*)(vr + 4);
        int2 c2 = *(const int2*)(vr + 8);
        float2 f0 = __half22float2(*(__half2*)&c0.x);
        float2 f1 = __half22float2(*(__half2*)&c0.y);
        float2 f2 = __half22float2(*(__half2*)&c1.x);
        float2 f3 = __half22float2(*(__half2*)&c1.y);
        float2 f4 = __half22float2(*(__half2*)&c2.x);
        float2 f5 = __half22float2(*(__half2*)&c2.y);

        float vv0 = pv01.x * wv0, vv1 = pv01.y * wv1;
        float vv2 = pv23.x * wv2, vv3 = pv23.y * wv3;
        float rr0 = pr01.x * wr0, rr1 = pr01.y * wr1;
        float rr2 = pr23.x * wr2, rr3 = pr23.y * wr3;
        ds4[0] += ps01.x * ws0; ds4[1] += ps01.y * ws1;
        ds4[2] += ps23.x * ws2; ds4[3] += ps23.y * ws3;

        float ux = geo.x, uy = geo.y, uz = geo.z;
        dv[0]  += f0.x * vv0 + rr0 * ux;
        dv[1]  += f0.y * vv0 + rr0 * uy;
        dv[2]  += f1.x * vv0 + rr0 * uz;
        dv[3]  += f1.y * vv1 + rr1 * ux;
        dv[4]  += f2.x * vv1 + rr1 * uy;
        dv[5]  += f2.y * vv1 + rr1 * uz;
        dv[6]  += f3.x * vv2 + rr2 * ux;
        dv[7]  += f3.y * vv2 + rr2 * uy;
        dv[8]  += f4.x * vv2 + rr2 * uz;
        dv[9]  += f4.y * vv3 + rr3 * ux;
        dv[10] += f5.x * vv3 + rr3 * uy;
        dv[11] += f5.y * vv3 + rr3 * uz;
    }
    const float4* vi = (const float4*)(v + (size_t)gw * 384);
    float4 b0 = vi[3 * lane + 0], b1 = vi[3 * lane + 1], b2 = vi[3 * lane + 2];
    b0.x += dv[0]; b0.y += dv[1]; b0.z += dv[2]; b0.w += dv[3];
    b1.x += dv[4]; b1.y += dv[5]; b1.z += dv[6]; b1.w += dv[7];
    b2.x += dv[8]; b2.y += dv[9]; b2.z += dv[10]; b2.w += dv[11];
    float4* vo = (float4*)(g_vnew + (size_t)gw * 384);
    vo[3 * lane + 0] = b0; vo[3 * lane + 1] = b1; vo[3 * lane + 2] = b2;

    {
        __half* vh2 = g_vnewh + (size_t)gw * 384 + 12 * lane;
        __half2 h0 = __floats2half2_rn(b0.x, b0.y);
        __half2 h1 = __floats2half2_rn(b0.z, b0.w);
        __half2 h2 = __floats2half2_rn(b1.x, b1.y);
        __half2 h3 = __floats2half2_rn(b1.z, b1.w);
        __half2 h4 = __floats2half2_rn(b2.x, b2.y);
        __half2 h5 = __floats2half2_rn(b2.z, b2.w);
        int2* d = (int2*)vh2;
        d[0] = make_int2(*(int*)&h0, *(int*)&h1);
        d[1] = make_int2(*(int*)&h2, *(int*)&h3);
        d[2] = make_int2(*(int*)&h4, *(int*)&h5);
    }

    float4 sv = ((const float4*)(s + (size_t)gw * 128))[lane];
    sv.x += ds4[0]; sv.y += ds4[1]; sv.z += ds4[2]; sv.w += ds4[3];
    ((float4*)(g_snew + (size_t)gw * 128))[lane] = sv;
}

// ---------------- pass 2 consumer + final combine: warp per node -----------
__global__ __launch_bounds__(256) void k_pass2(float* __restrict__ out, int N) {
    int gw = (blockIdx.x * blockDim.x + threadIdx.x) >> 5;
    int lane = threadIdx.x & 31;
    if (gw >= N) return;
    int beg = g_ptr[gw], end = g_ptr[gw + 1];
    int deg = end - beg;

    float uv[12];
    float smv[4], sms[4], smss[4];
#pragma unroll
    for (int k = 0; k < 12; k++) uv[k] = 0.0f;
#pragma unroll
    for (int k = 0; k < 4; k++) { smv[k] = 0.0f; sms[k] = 0.0f; smss[k] = 0.0f; }

#pragma unroll 2
    for (int p = beg; p < end; p++) {
        int sn = g_csr_src[p];
        const __half* vr = g_vnewh + (size_t)sn * 384 + 12 * lane;
        int2 c0 = *(const int2*)(vr);
        int2 c1 = *(const int2*)(vr + 4);
        int2 c2 = *(const int2*)(vr + 8);
        float2 f0 = __half22float2(*(__half2*)&c0.x);
        float2 f1 = __half22float2(*(__half2*)&c0.y);
        float2 f2 = __half22float2(*(__half2*)&c1.x);
        float2 f3 = __half22float2(*(__half2*)&c1.y);
        float2 f4 = __half22float2(*(__half2*)&c2.x);
        float2 f5 = __half22float2(*(__half2*)&c2.y);
        uv[0] += f0.x; uv[1] += f0.y; uv[2]  += f1.x; uv[3]  += f1.y;
        uv[4] += f2.x; uv[5] += f2.y; uv[6]  += f3.x; uv[7]  += f3.y;
        uv[8] += f4.x; uv[9] += f4.y; uv[10] += f5.x; uv[11] += f5.y;

        const __half* sr = g_s2h + (size_t)sn * 384;
        int2 q0 = *(const int2*)(sr + 4 * lane);
        int2 q1 = *(const int2*)(sr + 128 + 4 * lane);
        int2 q2 = *(const int2*)(sr + 256 + 4 * lane);
        float2 m01 = __half22float2(*(__half2*)&q0.x);
        float2 m23 = __half22float2(*(__half2*)&q0.y);
        float2 s01 = __half22float2(*(__half2*)&q1.x);
        float2 s23 = __half22float2(*(__half2*)&q1.y);
        float2 z01 = __half22float2(*(__half2*)&q2.x);
        float2 z23 = __half22float2(*(__half2*)&q2.y);
        smv[0]  += m01.x; smv[1]  += m01.y; smv[2]  += m23.x; smv[3]  += m23.y;
        sms[0]  += s01.x; sms[1]  += s01.y; sms[2]  += s23.x; sms[3]  += s23.y;
        smss[0] += z01.x; smss[1] += z01.y; smss[2] += z23.x; smss[3] += z23.y;
    }
    float inv = 1.0f / fmaxf((float)deg, 1.0f);
#pragma unroll
    for (int k = 0; k < 12; k++) uv[k] *= inv;
    float avv[4], asv[4], ass[4];
#pragma unroll
    for (int j = 0; j < 4; j++) {
        avv[j] = smv[j] * inv;
        asv[j] = sms[j] * inv;
        ass[j] = smss[j] * inv;
    }

    const float4* vi = (const float4*)(g_vnew + (size_t)gw * 384);
    float4 b0 = vi[3 * lane + 0], b1 = vi[3 * lane + 1], b2 = vi[3 * lane + 2];
    b0.x += uv[0] * avv[0]; b0.y += uv[1]  * avv[0]; b0.z += uv[2]  * avv[0];
    b0.w += uv[3] * avv[1]; b1.x += uv[4]  * avv[1]; b1.y += uv[5]  * avv[1];
    b1.z += uv[6] * avv[2]; b1.w += uv[7]  * avv[2]; b2.x += uv[8]  * avv[2];
    b2.y += uv[9] * avv[3]; b2.z += uv[10] * avv[3]; b2.w += uv[11] * avv[3];
    float4* vo = (float4*)(out + (size_t)gw * 384);
    vo[3 * lane + 0] = b0; vo[3 * lane + 1] = b1; vo[3 * lane + 2] = b2;

    float4 sn4 = ((const float4*)(g_snew + (size_t)gw * 128))[lane];
    float so[4];
#pragma unroll
    for (int j = 0; j < 4; j++) {
        float sx = uv[3 * j + 0], sy = uv[3 * j + 1], sz = uv[3 * j + 2];
        float ssq = sx * sx + sy * sy + sz * sz;
        float ratio = ssq / (ssq + 1e-5f);
        so[j] = ratio * asv[j] + ass[j];
    }
    sn4.x += so[0]; sn4.y += so[1]; sn4.z += so[2]; sn4.w += so[3];
    ((float4*)(out + (size_t)N * 384 + (size_t)gw * 128))[lane] = sn4;
}

// ---------------- launcher --------------------------------------------------
extern "C" void kernel_launch(void* const* d_in, const int* in_sizes, int n_in,
                              void* d_out, int out_size) {
    const float* x     = (const float*)d_in[0];
    const float* v     = (const float*)d_in[1];
    const float* s     = (const float*)d_in[2];
    const float* ms1_w = (const float*)d_in[3];
    const float* ms1_b = (const float*)d_in[4];
    const float* ms2_w = (const float*)d_in[5];
    const float* ms2_b = (const float*)d_in[6];
    const float* mv_w  = (const float*)d_in[7];
    const float* mv_b  = (const float*)d_in[8];
    const float* us1_w = (const float*)d_in[9];
    const float* us1_b = (const float*)d_in[10];
    const float* us2_w = (const float*)d_in[11];
    const float* us2_b = (const float*)d_in[12];
    const int*   src   = (const int*)d_in[13];
    const int*   dst   = (const int*)d_in[14];
    float* out = (float*)d_out;

    int N = in_sizes[0] / 3;
    int E = in_sizes[13];

    float *p_h, *p_snew;
    __half *p_phih, *p_s2h;
    int* p_deg;
    cudaGetSymbolAddress((void**)&p_h, g_h);
    cudaGetSymbolAddress((void**)&p_phih, g_phih);
    cudaGetSymbolAddress((void**)&p_snew, g_snew);
    cudaGetSymbolAddress((void**)&p_s2h, g_s2h);
    cudaGetSymbolAddress((void**)&p_deg, g_deg);

    // filter-weight table (independent of graph)
    k_wtab<<<TBL / 64, 128>>>(mv_w, mv_b);

    // CSR build + v->fp16 (combined hist+vhalf)
    cudaMemsetAsync(p_deg, 0, (size_t)N * sizeof(int));
    {
        int histBlocks = (E + 255) / 256;
        int vBlocks = (N * 384 / 8 + 255) / 256;
        k_hist_vhalf<<<histBlocks + vBlocks, 256>>>(dst, v, E, N * 384, histBlocks);
    }
    k_scan<<<1, 1024>>>(N);
    k_fill_edge<<<(E + 255) / 256, 256>>>(x, src, dst, E);

    // pass-1 node MLP (tf32 tensor cores), phi stored fp16
    {
        dim3 ga((N + 63) / 64, 128 / 64);
        k_mlp_tc<1, 0><<<ga, 128>>>(s, ms1_w, ms1_b, p_h, N, 128);
        dim3 gb((N + 63) / 64, 384 / 64);
        k_mlp_tc<0, 1><<<gb, 128>>>(p_h, ms2_w, ms2_b, p_phih, N, 384);
    }

    // pass-1 reduce (warp per node, table-interpolated w)
    k_pass1<<<(N * 32 + 255) / 256, 256>>>(v, s, N);

    // pass-2 node MLP on s_new (tf32 tensor cores), s2 stored fp16
    {
        dim3 ga((N + 63) / 64, 128 / 64);
        k_mlp_tc<1, 0><<<ga, 128>>>(p_snew, us1_w, us1_b, p_h, N, 128);
        dim3 gb((N + 63) / 64, 384 / 64);
        k_mlp_tc<0, 1><<<gb, 128>>>(p_h, us2_w, us2_b, p_s2h, N, 384);
    }

    // pass-2 reduce + final combine
    k_pass2<<<(N * 32 + 255) / 256, 256>>>(out, N);
}

// round 6
// speedup vs baseline: 1.9970x; 1.0004x over previous
#include <cuda_runtime.h>
#include <cuda_fp16.h>
#include <math.h>
#include <stdint.h>

#define NN 10000
#define EE 100000
#define TBL 8192
#define TBL_RMAX 25.0f

// ---------------- scratch (device globals; no allocation allowed) ----------
__device__ float  g_h[NN * 128];       // ssp(s@W1^T+b1) intermediate (fp32)
__device__ __half g_phih[NN * 384];    // pass-1 node MLP output (fp16)
__device__ __half g_vh[NN * 384];      // input v as fp16 (pass-1 gathers)
__device__ float  g_vnew[NN * 384];    // v_new fp32 (own-node reads + precision)
__device__ __half g_vnewh[NN * 384];   // v_new fp16 shadow (pass-2 gathers)
__device__ float  g_snew[NN * 128];    // s_new
__device__ __half g_s2h[NN * 384];     // pass-2 node MLP output (fp16)
__device__ __half g_wt[TBL * 384];     // filter weight lookup table over r (fp16)
__device__ float4 g_geo[EE];           // per-edge {unit.xyz, r} (CSR order)
__device__ int    g_deg[NN];
__device__ int    g_ptr[NN + 1];
__device__ int    g_fill[NN];
__device__ int    g_csr_src[EE];

// ---------------- helpers ---------------------------------------------------
__device__ __forceinline__ float sspf(float x) {
    float sp = fmaxf(x, 0.0f) + log1pf(expf(-fabsf(x)));
    return sp - 0.69314718055994531f;
}
__device__ __forceinline__ float fcf(float u) {
    return (u < 5.0f) ? 0.5f * (__cosf(0.6283185307179586f * u) + 1.0f) : 0.0f;
}
__device__ __forceinline__ uint32_t f2tf32(float f) {
    uint32_t r;
    asm("cvt.rna.tf32.f32 %0, %1;" : "=r"(r) : "f"(f));
    return r;
}
__device__ __forceinline__ void mma_tf32(float c[4], const uint32_t a[4], const uint32_t b[2]) {
    asm volatile(
        "mma.sync.aligned.m16n8k8.row.col.f32.tf32.tf32.f32 "
        "{%0,%1,%2,%3},{%4,%5,%6,%7},{%8,%9},{%0,%1,%2,%3};"
        : "+f"(c[0]), "+f"(c[1]), "+f"(c[2]), "+f"(c[3])
        : "r"(a[0]), "r"(a[1]), "r"(a[2]), "r"(a[3]), "r"(b[0]), "r"(b[1]));
}

// ---------------- combined: histogram + v->fp16 ------------------------------
__global__ void k_hist_vhalf(const int* __restrict__ dst, const float* __restrict__ v,
                             int E, int total, int histBlocks) {
    int b = blockIdx.x;
    if (b < histBlocks) {
        int e = b * 256 + threadIdx.x;
        if (e < E) atomicAdd(&g_deg[dst[e]], 1);
    } else {
        int i = ((b - histBlocks) * 256 + threadIdx.x) * 8;
        if (i >= total) return;
        float4 a = *(const float4*)(v + i);
        float4 c = *(const float4*)(v + i + 4);
        __half2 h0 = __floats2half2_rn(a.x, a.y);
        __half2 h1 = __floats2half2_rn(a.z, a.w);
        __half2 h2 = __floats2half2_rn(c.x, c.y);
        __half2 h3 = __floats2half2_rn(c.z, c.w);
        int4 o = make_int4(*(int*)&h0, *(int*)&h1, *(int*)&h2, *(int*)&h3);
        *(int4*)(g_vh + i) = o;
    }
}

// ---------------- prefix scan ------------------------------------------------
__global__ void k_scan(int N) {
    __shared__ int wsum[32];
    __shared__ int carry_s;
    int t = threadIdx.x, lane = t & 31, wid = t >> 5;
    if (t == 0) carry_s = 0;
    __syncthreads();
    for (int base = 0; base < N; base += 1024) {
        int i = base + t;
        int v = (i < N) ? g_deg[i] : 0;
        int x = v;
#pragma unroll
        for (int o = 1; o < 32; o <<= 1) {
            int y = __shfl_up_sync(0xFFFFFFFFu, x, o);
            if (lane >= o) x += y;
        }
        if (lane == 31) wsum[wid] = x;
        __syncthreads();
        if (wid == 0) {
            int w = wsum[lane];
#pragma unroll
            for (int o = 1; o < 32; o <<= 1) {
                int y = __shfl_up_sync(0xFFFFFFFFu, w, o);
                if (lane >= o) w += y;
            }
            wsum[lane] = w;
        }
        __syncthreads();
        int excl = x - v + (wid ? wsum[wid - 1] : 0) + carry_s;
        if (i < N) {
            g_ptr[i] = excl;
            g_fill[i] = excl;
        }
        int total = wsum[31];
        __syncthreads();
        if (t == 0) carry_s += total;
        __syncthreads();
    }
    if (threadIdx.x == 0) g_ptr[N] = carry_s;
}

// ---------------- fill + per-edge geometry (fused, no rbf) -------------------
__global__ void k_fill_edge(const float* __restrict__ x, const int* __restrict__ src,
                            const int* __restrict__ dst, int E) {
    int e = blockIdx.x * blockDim.x + threadIdx.x;
    if (e >= E) return;
    int d = dst[e];
    int sn = src[e];
    int pos = atomicAdd(&g_fill[d], 1);
    g_csr_src[pos] = sn;

    float vx = x[sn * 3 + 0] - x[d * 3 + 0];
    float vy = x[sn * 3 + 1] - x[d * 3 + 1];
    float vz = x[sn * 3 + 2] - x[d * 3 + 2];
    float r = sqrtf(vx * vx + vy * vy + vz * vz + 1e-5f);
    float inv = 1.0f / r;
    g_geo[pos] = make_float4(vx * inv, vy * inv, vz * inv, r);
}

// ---------------- filter weight table build: w(r) = fc(rbf(r)@mv_w^T + b) ----
// 128 blocks x 64 table rows, tf32 mma, loops 6 output tiles.
__global__ __launch_bounds__(128) void k_wtab(const float* __restrict__ mvw,
                                              const float* __restrict__ mvb) {
    __shared__ uint32_t As[64 * 28];
    __shared__ uint32_t Bs[64 * 28];
    int t = threadIdx.x;
    int warp = t >> 5, lane = t & 31;
    int gid = lane >> 2, tig = lane & 3;
    int wm = warp & 1, wn = warp >> 1;
    int p0 = blockIdx.x * 64;
    const float dR = TBL_RMAX / (float)TBL;

    // compute rbf rows directly for the 64 r values
    for (int i = t; i < 64 * 20; i += 128) {
        int row = i / 20, n = i - row * 20 + 1;
        float r = fmaxf((float)(p0 + row) * dR, 1e-4f);
        float val = (0.6324555320336759f / r) * sinf(0.6283185307179586f * r * (float)n);
        As[row * 28 + (n - 1)] = f2tf32(val);
    }
    for (int i = t; i < 64 * 8; i += 128) {
        int row = i >> 3, c = 20 + (i & 7);
        As[row * 28 + c] = 0;
        Bs[row * 28 + c] = 0;
    }

    for (int n0 = 0; n0 < 384; n0 += 64) {
        __syncthreads();
        for (int i = t; i < 64 * 20; i += 128) {
            int row = i / 20, c = i - row * 20;
            Bs[row * 28 + c] = f2tf32(mvw[(size_t)(n0 + row) * 20 + c]);
        }
        __syncthreads();

        float acc[2][4][4];
#pragma unroll
        for (int i = 0; i < 2; i++)
#pragma unroll
            for (int j = 0; j < 4; j++)
#pragma unroll
                for (int k = 0; k < 4; k++) acc[i][j][k] = 0.0f;

#pragma unroll
        for (int kc = 0; kc < 24; kc += 8) {
            uint32_t a[2][4], b[4][2];
#pragma unroll
            for (int ma = 0; ma < 2; ma++) {
                int r = wm * 32 + ma * 16 + gid;
                a[ma][0] = As[r * 28 + kc + tig];
                a[ma][1] = As[(r + 8) * 28 + kc + tig];
                a[ma][2] = As[r * 28 + kc + tig + 4];
                a[ma][3] = As[(r + 8) * 28 + kc + tig + 4];
            }
#pragma unroll
            for (int na = 0; na < 4; na++) {
                int cl = wn * 32 + na * 8 + gid;
                b[na][0] = Bs[cl * 28 + kc + tig];
                b[na][1] = Bs[cl * 28 + kc + tig + 4];
            }
#pragma unroll
            for (int ma = 0; ma < 2; ma++)
#pragma unroll
                for (int na = 0; na < 4; na++)
                    mma_tf32(acc[ma][na], a[ma], b[na]);
        }

#pragma unroll
        for (int ma = 0; ma < 2; ma++) {
#pragma unroll
            for (int na = 0; na < 4; na++) {
                int p = p0 + wm * 32 + ma * 16 + gid;
                int n = n0 + wn * 32 + na * 8 + 2 * tig;
                float bx = mvb[n], by = mvb[n + 1];
                float o0 = fcf(acc[ma][na][0] + bx), o1 = fcf(acc[ma][na][1] + by);
                float o2 = fcf(acc[ma][na][2] + bx), o3 = fcf(acc[ma][na][3] + by);
                *(__half2*)(g_wt + (size_t)p * 384 + n) = __floats2half2_rn(o0, o1);
                *(__half2*)(g_wt + (size_t)(p + 8) * 384 + n) = __floats2half2_rn(o2, o3);
            }
        }
    }
}

// ---------------- tf32 tensor-core node MLP: C = act(A[M,128] @ W[NOUT,128]^T + b)
template <int ACT, int HALF_OUT>
__global__ __launch_bounds__(128) void k_mlp_tc(const float* __restrict__ A,
                                                const float* __restrict__ W,
                                                const float* __restrict__ bias,
                                                void* __restrict__ Cv,
                                                int M, int NOUT) {
    __shared__ uint32_t As[64 * 68];
    __shared__ uint32_t Ws[64 * 68];
    int t = threadIdx.x;
    int warp = t >> 5, lane = t & 31;
    int gid = lane >> 2, tig = lane & 3;
    int wm = warp & 1, wn = warp >> 1;
    int m0 = blockIdx.x * 64, n0 = blockIdx.y * 64;

    float acc[2][4][4];
#pragma unroll
    for (int i = 0; i < 2; i++)
#pragma unroll
        for (int j = 0; j < 4; j++)
#pragma unroll
            for (int k = 0; k < 4; k++) acc[i][j][k] = 0.0f;

    for (int ks = 0; ks < 128; ks += 64) {
        __syncthreads();
        for (int i = t; i < 64 * 16; i += 128) {
            int row = i >> 4, c4 = (i & 15) << 2;
            float4 av = make_float4(0.f, 0.f, 0.f, 0.f);
            if (m0 + row < M)
                av = *(const float4*)(A + (size_t)(m0 + row) * 128 + ks + c4);
            uint32_t* da = &As[row * 68 + c4];
            da[0] = f2tf32(av.x); da[1] = f2tf32(av.y);
            da[2] = f2tf32(av.z); da[3] = f2tf32(av.w);
            float4 wv = *(const float4*)(W + (size_t)(n0 + row) * 128 + ks + c4);
            uint32_t* dw = &Ws[row * 68 + c4];
            dw[0] = f2tf32(wv.x); dw[1] = f2tf32(wv.y);
            dw[2] = f2tf32(wv.z); dw[3] = f2tf32(wv.w);
        }
        __syncthreads();
#pragma unroll
        for (int kc = 0; kc < 64; kc += 8) {
            uint32_t a[2][4], b[4][2];
#pragma unroll
            for (int ma = 0; ma < 2; ma++) {
                int r = wm * 32 + ma * 16 + gid;
                a[ma][0] = As[r * 68 + kc + tig];
                a[ma][1] = As[(r + 8) * 68 + kc + tig];
                a[ma][2] = As[r * 68 + kc + tig + 4];
                a[ma][3] = As[(r + 8) * 68 + kc + tig + 4];
            }
#pragma unroll
            for (int na = 0; na < 4; na++) {
                int cl = wn * 32 + na * 8 + gid;
                b[na][0] = Ws[cl * 68 + kc + tig];
                b[na][1] = Ws[cl * 68 + kc + tig + 4];
            }
#pragma unroll
            for (int ma = 0; ma < 2; ma++)
#pragma unroll
                for (int na = 0; na < 4; na++)
                    mma_tf32(acc[ma][na], a[ma], b[na]);
        }
    }
#pragma unroll
    for (int ma = 0; ma < 2; ma++) {
#pragma unroll
        for (int na = 0; na < 4; na++) {
            int m = m0 + wm * 32 + ma * 16 + gid;
            int n = n0 + wn * 32 + na * 8 + 2 * tig;
            float bx = bias[n], by = bias[n + 1];
            float o0 = acc[ma][na][0] + bx, o1 = acc[ma][na][1] + by;
            float o2 = acc[ma][na][2] + bx, o3 = acc[ma][na][3] + by;
            if (ACT) { o0 = sspf(o0); o1 = sspf(o1); o2 = sspf(o2); o3 = sspf(o3); }
            if (HALF_OUT) {
                __half* C = (__half*)Cv;
                if (m < M) *(__half2*)(C + (size_t)m * NOUT + n) = __floats2half2_rn(o0, o1);
                if (m + 8 < M) *(__half2*)(C + (size_t)(m + 8) * NOUT + n) = __floats2half2_rn(o2, o3);
            } else {
                float* C = (float*)Cv;
                if (m < M) *(float2*)(C + (size_t)m * NOUT + n) = make_float2(o0, o1);
                if (m + 8 < M) *(float2*)(C + (size_t)(m + 8) * NOUT + n) = make_float2(o2, o3);
            }
        }
    }
}

// ---------------- pass 1 consumer: warp per node, table-interpolated w -------
__global__ __launch_bounds__(256) void k_pass1(const float* __restrict__ v,
                                               const float* __restrict__ s, int N) {
    int gw = (blockIdx.x * blockDim.x + threadIdx.x) >> 5;
    int lane = threadIdx.x & 31;
    if (gw >= N) return;
    int beg = g_ptr[gw], end = g_ptr[gw + 1];
    float dv[12];
    float ds4[4];
#pragma unroll
    for (int k = 0; k < 12; k++) dv[k] = 0.0f;
#pragma unroll
    for (int k = 0; k < 4; k++) ds4[k] = 0.0f;

    const float invDR = (float)TBL / TBL_RMAX;

#pragma unroll 2
    for (int p = beg; p < end; p++) {
        int sn = g_csr_src[p];
        float4 geo = g_geo[p];   // uniform across warp (broadcast)
        float rt = fminf(geo.w * invDR, (float)TBL - 1.001f);
        int i0 = (int)rt;
        float fr = rt - (float)i0;

        const __half* ph = g_phih + (size_t)sn * 384;
        int2 t0 = *(const int2*)(ph + 4 * lane);
        int2 t1 = *(const int2*)(ph + 128 + 4 * lane);
        int2 t2 = *(const int2*)(ph + 256 + 4 * lane);
        float2 pv01 = __half22float2(*(__half2*)&t0.x);
        float2 pv23 = __half22float2(*(__half2*)&t0.y);
        float2 ps01 = __half22float2(*(__half2*)&t1.x);
        float2 ps23 = __half22float2(*(__half2*)&t1.y);
        float2 pr01 = __half22float2(*(__half2*)&t2.x);
        float2 pr23 = __half22float2(*(__half2*)&t2.y);

        const __half* wl = g_wt + (size_t)i0 * 384;
        int2 a0l = *(const int2*)(wl + 4 * lane);
        int2 a1l = *(const int2*)(wl + 128 + 4 * lane);
        int2 a2l = *(const int2*)(wl + 256 + 4 * lane);
        const __half* wh = wl + 384;
        int2 a0h = *(const int2*)(wh + 4 * lane);
        int2 a1h = *(const int2*)(wh + 128 + 4 * lane);
        int2 a2h = *(const int2*)(wh + 256 + 4 * lane);

        float2 l0 = __half22float2(*(__half2*)&a0l.x);
        float2 l1 = __half22float2(*(__half2*)&a0l.y);
        float2 h0 = __half22float2(*(__half2*)&a0h.x);
        float2 h1 = __half22float2(*(__half2*)&a0h.y);
        float wv0 = l0.x + fr * (h0.x - l0.x);
        float wv1 = l0.y + fr * (h0.y - l0.y);
        float wv2 = l1.x + fr * (h1.x - l1.x);
        float wv3 = l1.y + fr * (h1.y - l1.y);

        float2 sl0 = __half22float2(*(__half2*)&a1l.x);
        float2 sl1 = __half22float2(*(__half2*)&a1l.y);
        float2 sh0 = __half22float2(*(__half2*)&a1h.x);
        float2 sh1 = __half22float2(*(__half2*)&a1h.y);
        float ws0 = sl0.x + fr * (sh0.x - sl0.x);
        float ws1 = sl0.y + fr * (sh0.y - sl0.y);
        float ws2 = sl1.x + fr * (sh1.x - sl1.x);
        float ws3 = sl1.y + fr * (sh1.y - sl1.y);

        float2 rl0 = __half22float2(*(__half2*)&a2l.x);
        float2 rl1 = __half22float2(*(__half2*)&a2l.y);
        float2 rh0 = __half22float2(*(__half2*)&a2h.x);
        float2 rh1 = __half22float2(*(__half2*)&a2h.y);
        float wr0 = rl0.x + fr * (rh0.x - rl0.x);
        float wr1 = rl0.y + fr * (rh0.y - rl0.y);
        float wr2 = rl1.x + fr * (rh1.x - rl1.x);
        float wr3 = rl1.y + fr * (rh1.y - rl1.y);

        const __half* vr = g_vh + (size_t)sn * 384 + 12 * lane;
        int2 c0 = *(const int2*)(vr);
        int2 c1 = *(const int2*)(vr + 4);
        int2 c2 = *(const int2*)(vr + 8);
        float2 f0 = __half22float2(*(__half2*)&c0.x);
        float2 f1 = __half22float2(*(__half2*)&c0.y);
        float2 f2 = __half22float2(*(__half2*)&c1.x);
        float2 f3 = __half22float2(*(__half2*)&c1.y);
        float2 f4 = __half22float2(*(__half2*)&c2.x);
        float2 f5 = __half22float2(*(__half2*)&c2.y);

        float vv0 = pv01.x * wv0, vv1 = pv01.y * wv1;
        float vv2 = pv23.x * wv2, vv3 = pv23.y * wv3;
        float rr0 = pr01.x * wr0, rr1 = pr01.y * wr1;
        float rr2 = pr23.x * wr2, rr3 = pr23.y * wr3;
        ds4[0] += ps01.x * ws0; ds4[1] += ps01.y * ws1;
        ds4[2] += ps23.x * ws2; ds4[3] += ps23.y * ws3;

        float ux = geo.x, uy = geo.y, uz = geo.z;
        dv[0]  += f0.x * vv0 + rr0 * ux;
        dv[1]  += f0.y * vv0 + rr0 * uy;
        dv[2]  += f1.x * vv0 + rr0 * uz;
        dv[3]  += f1.y * vv1 + rr1 * ux;
        dv[4]  += f2.x * vv1 + rr1 * uy;
        dv[5]  += f2.y * vv1 + rr1 * uz;
        dv[6]  += f3.x * vv2 + rr2 * ux;
        dv[7]  += f3.y * vv2 + rr2 * uy;
        dv[8]  += f4.x * vv2 + rr2 * uz;
        dv[9]  += f4.y * vv3 + rr3 * ux;
        dv[10] += f5.x * vv3 + rr3 * uy;
        dv[11] += f5.y * vv3 + rr3 * uz;
    }
    const float4* vi = (const float4*)(v + (size_t)gw * 384);
    float4 b0 = vi[3 * lane + 0], b1 = vi[3 * lane + 1], b2 = vi[3 * lane + 2];
    b0.x += dv[0]; b0.y += dv[1]; b0.z += dv[2]; b0.w += dv[3];
    b1.x += dv[4]; b1.y += dv[5]; b1.z += dv[6]; b1.w += dv[7];
    b2.x += dv[8]; b2.y += dv[9]; b2.z += dv[10]; b2.w += dv[11];
    float4* vo = (float4*)(g_vnew + (size_t)gw * 384);
    vo[3 * lane + 0] = b0; vo[3 * lane + 1] = b1; vo[3 * lane + 2] = b2;

    {
        __half* vh2 = g_vnewh + (size_t)gw * 384 + 12 * lane;
        __half2 h0 = __floats2half2_rn(b0.x, b0.y);
        __half2 h1 = __floats2half2_rn(b0.z, b0.w);
        __half2 h2 = __floats2half2_rn(b1.x, b1.y);
        __half2 h3 = __floats2half2_rn(b1.z, b1.w);
        __half2 h4 = __floats2half2_rn(b2.x, b2.y);
        __half2 h5 = __floats2half2_rn(b2.z, b2.w);
        int2* d = (int2*)vh2;
        d[0] = make_int2(*(int*)&h0, *(int*)&h1);
        d[1] = make_int2(*(int*)&h2, *(int*)&h3);
        d[2] = make_int2(*(int*)&h4, *(int*)&h5);
    }

    float4 sv = ((const float4*)(s + (size_t)gw * 128))[lane];
    sv.x += ds4[0]; sv.y += ds4[1]; sv.z += ds4[2]; sv.w += ds4[3];
    ((float4*)(g_snew + (size_t)gw * 128))[lane] = sv;
}

// ---------------- pass 2 consumer + final combine: warp per node -----------
__global__ __launch_bounds__(256) void k_pass2(float* __restrict__ out, int N) {
    int gw = (blockIdx.x * blockDim.x + threadIdx.x) >> 5;
    int lane = threadIdx.x & 31;
    if (gw >= N) return;
    int beg = g_ptr[gw], end = g_ptr[gw + 1];
    int deg = end - beg;

    float uv[12];
    float smv[4], sms[4], smss[4];
#pragma unroll
    for (int k = 0; k < 12; k++) uv[k] = 0.0f;
#pragma unroll
    for (int k = 0; k < 4; k++) { smv[k] = 0.0f; sms[k] = 0.0f; smss[k] = 0.0f; }

#pragma unroll 2
    for (int p = beg; p < end; p++) {
        int sn = g_csr_src[p];
        const __half* vr = g_vnewh + (size_t)sn * 384 + 12 * lane;
        int2 c0 = *(const int2*)(vr);
        int2 c1 = *(const int2*)(vr + 4);
        int2 c2 = *(const int2*)(vr + 8);
        float2 f0 = __half22float2(*(__half2*)&c0.x);
        float2 f1 = __half22float2(*(__half2*)&c0.y);
        float2 f2 = __half22float2(*(__half2*)&c1.x);
        float2 f3 = __half22float2(*(__half2*)&c1.y);
        float2 f4 = __half22float2(*(__half2*)&c2.x);
        float2 f5 = __half22float2(*(__half2*)&c2.y);
        uv[0] += f0.x; uv[1] += f0.y; uv[2]  += f1.x; uv[3]  += f1.y;
        uv[4] += f2.x; uv[5] += f2.y; uv[6]  += f3.x; uv[7]  += f3.y;
        uv[8] += f4.x; uv[9] += f4.y; uv[10] += f5.x; uv[11] += f5.y;

        const __half* sr = g_s2h + (size_t)sn * 384;
        int2 q0 = *(const int2*)(sr + 4 * lane);
        int2 q1 = *(const int2*)(sr + 128 + 4 * lane);
        int2 q2 = *(const int2*)(sr + 256 + 4 * lane);
        float2 m01 = __half22float2(*(__half2*)&q0.x);
        float2 m23 = __half22float2(*(__half2*)&q0.y);
        float2 s01 = __half22float2(*(__half2*)&q1.x);
        float2 s23 = __half22float2(*(__half2*)&q1.y);
        float2 z01 = __half22float2(*(__half2*)&q2.x);
        float2 z23 = __half22float2(*(__half2*)&q2.y);
        smv[0]  += m01.x; smv[1]  += m01.y; smv[2]  += m23.x; smv[3]  += m23.y;
        sms[0]  += s01.x; sms[1]  += s01.y; sms[2]  += s23.x; sms[3]  += s23.y;
        smss[0] += z01.x; smss[1] += z01.y; smss[2] += z23.x; smss[3] += z23.y;
    }
    float inv = 1.0f / fmaxf((float)deg, 1.0f);
#pragma unroll
    for (int k = 0; k < 12; k++) uv[k] *= inv;
    float avv[4], asv[4], ass[4];
#pragma unroll
    for (int j = 0; j < 4; j++) {
        avv[j] = smv[j] * inv;
        asv[j] = sms[j] * inv;
        ass[j] = smss[j] * inv;
    }

    const float4* vi = (const float4*)(g_vnew + (size_t)gw * 384);
    float4 b0 = vi[3 * lane + 0], b1 = vi[3 * lane + 1], b2 = vi[3 * lane + 2];
    b0.x += uv[0] * avv[0]; b0.y += uv[1]  * avv[0]; b0.z += uv[2]  * avv[0];
    b0.w += uv[3] * avv[1]; b1.x += uv[4]  * avv[1]; b1.y += uv[5]  * avv[1];
    b1.z += uv[6] * avv[2]; b1.w += uv[7]  * avv[2]; b2.x += uv[8]  * avv[2];
    b2.y += uv[9] * avv[3]; b2.z += uv[10] * avv[3]; b2.w += uv[11] * avv[3];
    float4* vo = (float4*)(out + (size_t)gw * 384);
    vo[3 * lane + 0] = b0; vo[3 * lane + 1] = b1; vo[3 * lane + 2] = b2;

    float4 sn4 = ((const float4*)(g_snew + (size_t)gw * 128))[lane];
    float so[4];
#pragma unroll
    for (int j = 0; j < 4; j++) {
        float sx = uv[3 * j + 0], sy = uv[3 * j + 1], sz = uv[3 * j + 2];
        float ssq = sx * sx + sy * sy + sz * sz;
        float ratio = ssq / (ssq + 1e-5f);
        so[j] = ratio * asv[j] + ass[j];
    }
    sn4.x += so[0]; sn4.y += so[1]; sn4.z += so[2]; sn4.w += so[3];
    ((float4*)(out + (size_t)N * 384 + (size_t)gw * 128))[lane] = sn4;
}

// ---------------- launcher --------------------------------------------------
extern "C" void kernel_launch(void* const* d_in, const int* in_sizes, int n_in,
                              void* d_out, int out_size) {
    const float* x     = (const float*)d_in[0];
    const float* v     = (const float*)d_in[1];
    const float* s     = (const float*)d_in[2];
    const float* ms1_w = (const float*)d_in[3];
    const float* ms1_b = (const float*)d_in[4];
    const float* ms2_w = (const float*)d_in[5];
    const float* ms2_b = (const float*)d_in[6];
    const float* mv_w  = (const float*)d_in[7];
    const float* mv_b  = (const float*)d_in[8];
    const float* us1_w = (const float*)d_in[9];
    const float* us1_b = (const float*)d_in[10];
    const float* us2_w = (const float*)d_in[11];
    const float* us2_b = (const float*)d_in[12];
    const int*   src   = (const int*)d_in[13];
    const int*   dst   = (const int*)d_in[14];
    float* out = (float*)d_out;

    int N = in_sizes[0] / 3;
    int E = in_sizes[13];

    float *p_h, *p_snew;
    __half *p_phih, *p_s2h;
    int* p_deg;
    cudaGetSymbolAddress((void**)&p_h, g_h);
    cudaGetSymbolAddress((void**)&p_phih, g_phih);
    cudaGetSymbolAddress((void**)&p_snew, g_snew);
    cudaGetSymbolAddress((void**)&p_s2h, g_s2h);
    cudaGetSymbolAddress((void**)&p_deg, g_deg);

    // filter-weight table (independent of graph)
    k_wtab<<<TBL / 64, 128>>>(mv_w, mv_b);

    // CSR build + v->fp16 (combined hist+vhalf)
    cudaMemsetAsync(p_deg, 0, (size_t)N * sizeof(int));
    {
        int histBlocks = (E + 255) / 256;
        int vBlocks = (N * 384 / 8 + 255) / 256;
        k_hist_vhalf<<<histBlocks + vBlocks, 256>>>(dst, v, E, N * 384, histBlocks);
    }
    k_scan<<<1, 1024>>>(N);
    k_fill_edge<<<(E + 255) / 256, 256>>>(x, src, dst, E);

    // pass-1 node MLP (tf32 tensor cores), phi stored fp16
    {
        dim3 ga((N + 63) / 64, 128 / 64);
        k_mlp_tc<1, 0><<<ga, 128>>>(s, ms1_w, ms1_b, p_h, N, 128);
        dim3 gb((N + 63) / 64, 384 / 64);
        k_mlp_tc<0, 1><<<gb, 128>>>(p_h, ms2_w, ms2_b, p_phih, N, 384);
    }

    // pass-1 reduce (warp per node, table-interpolated w)
    k_pass1<<<(N * 32 + 255) / 256, 256>>>(v, s, N);

    // pass-2 node MLP on s_new (tf32 tensor cores), s2 stored fp16
    {
        dim3 ga((N + 63) / 64, 128 / 64);
        k_mlp_tc<1, 0><<<ga, 128>>>(p_snew, us1_w, us1_b, p_h, N, 128);
        dim3 gb((N + 63) / 64, 384 / 64);
        k_mlp_tc<0, 1><<<gb, 128>>>(p_h, us2_w, us2_b, p_s2h, N, 384);
    }

    // pass-2 reduce + final combine
    k_pass2<<<(N * 32 + 255) / 256, 256>>>(out, N);
}